// round 12
// baseline (speedup 1.0000x reference)
#include <cuda_runtime.h>
#include <math.h>
#include <stdint.h>

// ---------------- problem constants ----------------
#define Bb     2
#define Ss     2048
#define DIMc   2048
#define Hh     16
#define QLORA  1536
#define KVLORA 512
#define NOPEc  128
#define ROPEc  64
#define VDIMc  128
#define QKH    192            // NOPE + ROPE
#define ROWS   (Bb*Ss)        // 4096
#define DF     576            // 512 latent + 64 rope
#define SCALEc 0.07216878364870322f  // 1/sqrt(192)
#define EPSc   1e-6f

// ---------------- scratch (static device arrays; no allocation) ----------------
__device__ float g_qlat[(size_t)ROWS * QLORA];          // 4096 x 1536
__device__ float g_q[(size_t)ROWS * (Hh * QKH)];        // 4096 x 3072
__device__ float g_kv[(size_t)ROWS * DF];               // 4096 x 576
__device__ float g_kfull[(size_t)ROWS * DF];            // 4096 x 576 (tf32-rounded)
__device__ float g_qfull[(size_t)ROWS * Hh * DF];       // 4096 x 16 x 576 (tf32-rounded)
__device__ float g_ctx[(size_t)ROWS * Hh * KVLORA];     // 4096 x 16 x 512
__device__ float g_attnout[(size_t)ROWS * DIMc];        // 4096 x 2048
__device__ float g_wkvbT[(size_t)Hh * KVLORA * NOPEc];  // 16 x 512 x 128 (transposed nope half)

// ================= tf32 helpers =================
__device__ __forceinline__ uint32_t f2tf(float x) {
    uint32_t r;
    asm("cvt.rna.tf32.f32 %0, %1;" : "=r"(r) : "f"(x));
    return r;
}
__device__ __forceinline__ float f2tf_f(float x) { return __uint_as_float(f2tf(x)); }
__device__ __forceinline__ void mma_tf32(float* d, const uint32_t* a, const uint32_t* b) {
    asm volatile(
        "mma.sync.aligned.m16n8k8.row.col.f32.tf32.tf32.f32 "
        "{%0,%1,%2,%3}, {%4,%5,%6,%7}, {%8,%9}, {%0,%1,%2,%3};"
        : "+f"(d[0]), "+f"(d[1]), "+f"(d[2]), "+f"(d[3])
        : "r"(a[0]), "r"(a[1]), "r"(a[2]), "r"(a[3]), "r"(b[0]), "r"(b[1]));
}
__device__ __forceinline__ uint32_t smem_u32(const void* p) {
    uint32_t a;
    asm("{ .reg .u64 t; cvta.to.shared.u64 t, %1; cvt.u32.u64 %0, t; }" : "=r"(a) : "l"(p));
    return a;
}
__device__ __forceinline__ void cpa16(uint32_t dst, const void* src) {
    asm volatile("cp.async.cg.shared.global [%0], [%1], 16;" :: "r"(dst), "l"(src));
}

// ================= tf32 tensor-core GEMM (TB: C = A @ B^T) =================
// 256 threads, 8 warps (2x4), 128x128 block tile, BK=16, warp tile 64x32.
// (R6/R7/R9-verified config: 125 regs, 2 CTAs/SM.)
// ROUND: tf32-round outputs in epilogue (used when C feeds attention as mma operand).
template<int ROUND>
__global__ __launch_bounds__(256) void gemm_tc_kernel(
    const float* __restrict__ A, int lda, long sA_,
    const float* __restrict__ B, int ldb, long sB_,
    float* __restrict__ C, int ldc, long sC_,
    int M, int N, int K)
{
    __shared__ __align__(16) uint32_t sA[2][2048];
    __shared__ __align__(16) uint32_t sB[2][2048];

    int z = blockIdx.z;
    A += (size_t)z * sA_;
    B += (size_t)z * sB_;
    C += (size_t)z * sC_;

    const int tid    = threadIdx.x;
    const int lane   = tid & 31;
    const int warp   = tid >> 5;
    const int warp_m = warp >> 2;      // 0..1
    const int warp_n = warp & 3;       // 0..3
    const int g = lane >> 2, t = lane & 3;
    const int m0 = blockIdx.y * 128;
    const int n0 = blockIdx.x * 128;
    const int KT = K >> 4;

    float acc[4][4][4];
#pragma unroll
    for (int mt = 0; mt < 4; mt++)
#pragma unroll
        for (int nt = 0; nt < 4; nt++)
#pragma unroll
            for (int e = 0; e < 4; e++) acc[mt][nt][e] = 0.f;

    float4 av[2], bv[2];
    const int lr0 = tid >> 2;          // row 0..63 (pass 0), +64 (pass 1)
    const int lkc = (tid & 3) << 2;    // k offset 0/4/8/12

    auto loadT = [&](int kt) {
        int k0 = kt << 4;
#pragma unroll
        for (int i = 0; i < 2; i++) {
            int r = lr0 + i * 64;
            av[i] = *(const float4*)(A + (size_t)(m0 + r) * lda + k0 + lkc);
            float4 v = make_float4(0.f, 0.f, 0.f, 0.f);
            if (n0 + r < N) v = *(const float4*)(B + (size_t)(n0 + r) * ldb + k0 + lkc);
            bv[i] = v;
        }
    };

    auto storeT = [&](int buf) {
#pragma unroll
        for (int i = 0; i < 2; i++) {
            int r = lr0 + i * 64;
            int xc = lkc ^ (((r >> 1) & 3) << 2);
            uint4 ta;
            ta.x = f2tf(av[i].x); ta.y = f2tf(av[i].y);
            ta.z = f2tf(av[i].z); ta.w = f2tf(av[i].w);
            *(uint4*)&sA[buf][r * 16 + xc] = ta;
            uint4 tb;
            tb.x = f2tf(bv[i].x); tb.y = f2tf(bv[i].y);
            tb.z = f2tf(bv[i].z); tb.w = f2tf(bv[i].w);
            *(uint4*)&sB[buf][r * 16 + xc] = tb;
        }
    };

    const int fr = (g >> 1) << 2;      // fragment-row swizzle

    auto compute = [&](int buf) {
#pragma unroll
        for (int ks = 0; ks < 2; ks++) {
            const int xk  = ((ks << 3) | t) ^ fr;
            const int xk2 = xk ^ 4;
            uint32_t af[4][4];
            uint32_t bf[4][2];
#pragma unroll
            for (int mt = 0; mt < 4; mt++) {
                int base = (warp_m * 64 + mt * 16 + g) * 16;
                af[mt][0] = sA[buf][base + xk];
                af[mt][1] = sA[buf][base + 128 + xk];
                af[mt][2] = sA[buf][base + xk2];
                af[mt][3] = sA[buf][base + 128 + xk2];
            }
#pragma unroll
            for (int nt = 0; nt < 4; nt++) {
                int base = (warp_n * 32 + nt * 8 + g) * 16;
                bf[nt][0] = sB[buf][base + xk];
                bf[nt][1] = sB[buf][base + xk2];
            }
#pragma unroll
            for (int mt = 0; mt < 4; mt++)
#pragma unroll
                for (int nt = 0; nt < 4; nt++)
                    mma_tf32(acc[mt][nt], af[mt], bf[nt]);
        }
    };

    loadT(0);
    storeT(0);
    __syncthreads();
    if (KT > 1) loadT(1);

    for (int kt = 0; kt < KT; kt++) {
        int cur = kt & 1;
        compute(cur);
        if (kt + 1 < KT) storeT(1 - cur);
        __syncthreads();
        if (kt + 2 < KT) loadT(kt + 2);
    }

    // ---- epilogue ----
#pragma unroll
    for (int mt = 0; mt < 4; mt++) {
        int row0 = m0 + warp_m * 64 + mt * 16 + g;
#pragma unroll
        for (int nt = 0; nt < 4; nt++) {
            int col = n0 + warp_n * 32 + nt * 8 + 2 * t;
            if (col < N) {
                float2 v0, v1;
                if (ROUND) {
                    v0 = make_float2(f2tf_f(acc[mt][nt][0]), f2tf_f(acc[mt][nt][1]));
                    v1 = make_float2(f2tf_f(acc[mt][nt][2]), f2tf_f(acc[mt][nt][3]));
                } else {
                    v0 = make_float2(acc[mt][nt][0], acc[mt][nt][1]);
                    v1 = make_float2(acc[mt][nt][2], acc[mt][nt][3]);
                }
                *(float2*)(C + (size_t)row0 * ldc + col) = v0;
                *(float2*)(C + (size_t)(row0 + 8) * ldc + col) = v1;
            }
        }
    }
}

// ---------------- transpose wkv_b nope half: out[h][c][d] = wkv_b[h*256+d][c] ----------------
__global__ __launch_bounds__(256) void transpose_wkvb_kernel(
    const float* __restrict__ w, float* __restrict__ out)
{
    __shared__ float tile[32][33];
    int h = blockIdx.z;
    int c0 = blockIdx.x * 32;
    int d0 = blockIdx.y * 32;
    int tx = threadIdx.x & 31, ty = threadIdx.x >> 5;
#pragma unroll
    for (int i = ty; i < 32; i += 8)
        tile[i][tx] = w[((size_t)h * 256 + d0 + i) * KVLORA + c0 + tx];
    __syncthreads();
#pragma unroll
    for (int i = ty; i < 32; i += 8)
        out[((size_t)h * KVLORA + c0 + i) * NOPEc + d0 + tx] = tile[tx][i];
}

// ---------------- RMSNorm (in-place, one block per row) ----------------
__global__ __launch_bounds__(256) void rmsnorm_kernel(
    float* __restrict__ x, const float* __restrict__ w, int L)
{
    __shared__ float sbuf[8];
    int row = blockIdx.x;
    float* xr = x + (size_t)row * L;
    float ss = 0.f;
    for (int i = threadIdx.x; i < L; i += 256) { float v = xr[i]; ss += v * v; }
#pragma unroll
    for (int o = 16; o; o >>= 1) ss += __shfl_xor_sync(0xffffffffu, ss, o);
    int warp = threadIdx.x >> 5, lane = threadIdx.x & 31;
    if (lane == 0) sbuf[warp] = ss;
    __syncthreads();
    if (threadIdx.x == 0) {
        float t = 0.f;
#pragma unroll
        for (int i = 0; i < 8; i++) t += sbuf[i];
        sbuf[0] = rsqrtf(t / (float)L + EPSc);
    }
    __syncthreads();
    float sc = sbuf[0];
    for (int i = threadIdx.x; i < L; i += 256) xr[i] = xr[i] * sc * w[i];
}

// ---------------- kv split: rmsnorm(latent) + rope(k_pe) -> kfull (tf32-rounded) ----------------
__global__ __launch_bounds__(256) void kvprep_kernel(
    const float* __restrict__ kv, const float* __restrict__ w,
    const float* __restrict__ fcos, const float* __restrict__ fsin,
    float* __restrict__ kfull)
{
    __shared__ float sbuf[8];
    int row = blockIdx.x;
    int s = row & (Ss - 1);
    const float* kr = kv + (size_t)row * DF;
    float* kf = kfull + (size_t)row * DF;

    float ss = 0.f;
    for (int i = threadIdx.x; i < KVLORA; i += 256) { float v = kr[i]; ss += v * v; }
#pragma unroll
    for (int o = 16; o; o >>= 1) ss += __shfl_xor_sync(0xffffffffu, ss, o);
    int warp = threadIdx.x >> 5, lane = threadIdx.x & 31;
    if (lane == 0) sbuf[warp] = ss;
    __syncthreads();
    if (threadIdx.x == 0) {
        float t = 0.f;
#pragma unroll
        for (int i = 0; i < 8; i++) t += sbuf[i];
        sbuf[0] = rsqrtf(t / (float)KVLORA + EPSc);
    }
    __syncthreads();
    float sc = sbuf[0];
    for (int i = threadIdx.x; i < KVLORA; i += 256) kf[i] = f2tf_f(kr[i] * sc * w[i]);

    if (threadIdx.x < 32) {
        int i = threadIdx.x;
        float x0 = kr[KVLORA + 2 * i], x1 = kr[KVLORA + 2 * i + 1];
        float c = fcos[s * 32 + i], sn = fsin[s * 32 + i];
        kf[KVLORA + 2 * i]     = f2tf_f(x0 * c - x1 * sn);
        kf[KVLORA + 2 * i + 1] = f2tf_f(x0 * sn + x1 * c);
    }
}

// ---------------- rope(q_pe) -> qfull[:, :, 512:576] (tf32-rounded) ----------------
__global__ __launch_bounds__(512) void ropeq_kernel(
    const float* __restrict__ q, const float* __restrict__ fcos,
    const float* __restrict__ fsin, float* __restrict__ qfull)
{
    int row = blockIdx.x;
    int s = row & (Ss - 1);
    int t = threadIdx.x;       // 512 = 16 heads * 32 pairs
    int h = t >> 5, i = t & 31;
    const float* qr = q + (size_t)row * (Hh * QKH) + h * QKH + NOPEc;
    float x0 = qr[2 * i], x1 = qr[2 * i + 1];
    float c = fcos[s * 32 + i], sn = fsin[s * 32 + i];
    float* dst = qfull + ((size_t)row * Hh + h) * DF + KVLORA;
    dst[2 * i]     = f2tf_f(x0 * c - x1 * sn);
    dst[2 * i + 1] = f2tf_f(x0 * sn + x1 * c);
}

// ---------------- flash attention (tf32 mma, 32q x 32k tiles, 4-way k-split) ----------------
// Inputs qfull/kfull are pre-rounded to tf32 -> tile loads are raw cp.async copies.
#define KSTR 588
#define PSTR 36
#define ATTN_SMEM_BYTES ((2 * 32 * KSTR + 4 * 32 * PSTR + 64) * 4)

__global__ __launch_bounds__(256, 1) void attn_kernel(
    const float* __restrict__ qfull, const float* __restrict__ kfull,
    float* __restrict__ ctx)
{
    extern __shared__ float sm[];
    float* Qs   = sm;                   // 32 x 588 (tf32)
    float* Ks   = sm + 32 * KSTR;       // 32 x 588 (tf32; cols 0..511 double as V)
    float* Ps   = Ks + 32 * KSTR;       // 4 buffers of 32 x 36 (score partials; buf 0 reused as P)
    float* arow = Ps + 4 * 32 * PSTR;   // 32
    float* lrow = arow + 32;            // 32

    const int tid  = threadIdx.x;
    const int lane = tid & 31, warp = tid >> 5;
    const int g = lane >> 2, t = lane & 3;
    // score roles: 2(m) x 4(k-split); each warp does full n32
    const int wk = warp & 3, wm = warp >> 2;
    const int bh = blockIdx.y;
    const int b = bh >> 4, h = bh & 15;
    const int s0 = blockIdx.x * 32;

    const int trow = tid >> 3, t8 = tid & 7;   // copy roles: 8 threads per row, 18 x 16B each
    const uint32_t qdst = smem_u32(Qs) + ((uint32_t)trow * KSTR + (uint32_t)t8 * 4) * 4;
    const uint32_t kdst = smem_u32(Ks) + ((uint32_t)trow * KSTR + (uint32_t)t8 * 4) * 4;

    // ---- load Q tile (async copy; pre-rounded) ----
    {
        const float4* src = (const float4*)(qfull + ((size_t)(b * Ss + s0 + trow) * Hh + h) * DF) + t8;
#pragma unroll
        for (int c = 0; c < 18; c++) cpa16(qdst + c * 128, src + c * 8);
        asm volatile("cp.async.commit_group;" ::: "memory");
    }

    float oacc[2][8][4];
#pragma unroll
    for (int mt = 0; mt < 2; mt++)
#pragma unroll
        for (int nt = 0; nt < 8; nt++)
#pragma unroll
            for (int e = 0; e < 4; e++) oacc[mt][nt][e] = 0.f;

    float mreg[4], lreg[4];
#pragma unroll
    for (int ii = 0; ii < 4; ii++) { mreg[ii] = -INFINITY; lreg[ii] = 0.f; }

    const int ntiles = s0 / 32 + 1;
    for (int kt = 0; kt < ntiles; kt++) {
        int t0 = kt * 32;
        // ---- load K tile (async copy; pre-rounded) ----
        {
            const float4* src = (const float4*)(kfull + (size_t)(b * Ss + t0 + trow) * DF) + t8;
#pragma unroll
            for (int c = 0; c < 18; c++) cpa16(kdst + c * 128, src + c * 8);
            asm volatile("cp.async.commit_group;" ::: "memory");
            asm volatile("cp.async.wait_group 0;" ::: "memory");
        }
        __syncthreads();

        // ---- scores: warp (wm, wk) -> m16 x n32 tile, k-quarter wk (144 each) ----
        {
            float sacc[4][4];
#pragma unroll
            for (int nt = 0; nt < 4; nt++)
#pragma unroll
                for (int e = 0; e < 4; e++) sacc[nt][e] = 0.f;

            const float* qb0 = Qs + (wm * 16 + g) * KSTR + wk * 144 + t;
#pragma unroll 3
            for (int ks = 0; ks < 18; ks++) {
                const float* qb = qb0 + ks * 8;
                uint32_t a[4];
                a[0] = __float_as_uint(qb[0]);
                a[1] = __float_as_uint(qb[8 * KSTR]);
                a[2] = __float_as_uint(qb[4]);
                a[3] = __float_as_uint(qb[8 * KSTR + 4]);
#pragma unroll
                for (int nt = 0; nt < 4; nt++) {
                    const float* kb = Ks + (nt * 8 + g) * KSTR + wk * 144 + ks * 8 + t;
                    uint32_t bf[2];
                    bf[0] = __float_as_uint(kb[0]);
                    bf[1] = __float_as_uint(kb[4]);
                    mma_tf32(sacc[nt], a, bf);
                }
            }
            float* Pw = Ps + wk * 32 * PSTR;
#pragma unroll
            for (int nt = 0; nt < 4; nt++) {
                int colb = nt * 8 + 2 * t;
                *(float2*)&Pw[(wm * 16 + g) * PSTR + colb] =
                    make_float2(sacc[nt][0], sacc[nt][1]);
                *(float2*)&Pw[(wm * 16 + g + 8) * PSTR + colb] =
                    make_float2(sacc[nt][2], sacc[nt][3]);
            }
        }
        __syncthreads();

        // ---- softmax: warp owns rows 4*warp..+3, lane = key j ----
        {
#pragma unroll
            for (int ii = 0; ii < 4; ii++) {
                int i = warp * 4 + ii;
                float v = (Ps[i * PSTR + lane] +
                           Ps[32 * PSTR + i * PSTR + lane] +
                           Ps[64 * PSTR + i * PSTR + lane] +
                           Ps[96 * PSTR + i * PSTR + lane]) * SCALEc;
                if (t0 + lane > s0 + i) v = -INFINITY;
                float mx = v;
#pragma unroll
                for (int o = 16; o; o >>= 1) mx = fmaxf(mx, __shfl_xor_sync(0xffffffffu, mx, o));
                float mnew = fmaxf(mreg[ii], mx);
                float p = __expf(v - mnew);
                float psum = p;
#pragma unroll
                for (int o = 16; o; o >>= 1) psum += __shfl_xor_sync(0xffffffffu, psum, o);
                float al = __expf(mreg[ii] - mnew);
                lreg[ii] = lreg[ii] * al + psum;
                mreg[ii] = mnew;
                Ps[i * PSTR + lane] = f2tf_f(p);
                if (lane == 0) arow[i] = al;
            }
        }
        __syncthreads();

        // ---- PV: warp owns all 32 rows x cols [warp*64, warp*64+64) ----
        {
#pragma unroll
            for (int mt = 0; mt < 2; mt++) {
                float al0 = arow[mt * 16 + g];
                float al1 = arow[mt * 16 + g + 8];
#pragma unroll
                for (int nt = 0; nt < 8; nt++) {
                    oacc[mt][nt][0] *= al0; oacc[mt][nt][1] *= al0;
                    oacc[mt][nt][2] *= al1; oacc[mt][nt][3] *= al1;
                }
            }
#pragma unroll
            for (int jb = 0; jb < 4; jb++) {
                int j0 = jb * 8;
                uint32_t pa[2][4];
#pragma unroll
                for (int mt = 0; mt < 2; mt++) {
                    const float* pb = Ps + (mt * 16 + g) * PSTR + j0 + t;
                    pa[mt][0] = __float_as_uint(pb[0]);
                    pa[mt][1] = __float_as_uint(pb[8 * PSTR]);
                    pa[mt][2] = __float_as_uint(pb[4]);
                    pa[mt][3] = __float_as_uint(pb[8 * PSTR + 4]);
                }
#pragma unroll
                for (int nt = 0; nt < 8; nt++) {
                    const float* vbp = Ks + (j0 + t) * KSTR + warp * 64 + nt * 8 + g;
                    uint32_t vb[2];
                    vb[0] = __float_as_uint(vbp[0]);
                    vb[1] = __float_as_uint(vbp[4 * KSTR]);
                    mma_tf32(oacc[0][nt], pa[0], vb);
                    mma_tf32(oacc[1][nt], pa[1], vb);
                }
            }
        }
        __syncthreads();
    }

    // ---- publish l, normalize, store ctx ----
    if (lane == 0) {
#pragma unroll
        for (int ii = 0; ii < 4; ii++) lrow[warp * 4 + ii] = lreg[ii];
    }
    __syncthreads();
#pragma unroll
    for (int mt = 0; mt < 2; mt++) {
        int r0 = mt * 16 + g;
        int r1 = mt * 16 + g + 8;
        float inv0 = 1.0f / lrow[r0];
        float inv1 = 1.0f / lrow[r1];
        float* cp0 = ctx + ((size_t)(b * Ss + s0 + r0) * Hh + h) * KVLORA + warp * 64;
        float* cp1 = ctx + ((size_t)(b * Ss + s0 + r1) * Hh + h) * KVLORA + warp * 64;
#pragma unroll
        for (int nt = 0; nt < 8; nt++) {
            int col = nt * 8 + 2 * t;
            *(float2*)(cp0 + col) = make_float2(oacc[mt][nt][0] * inv0, oacc[mt][nt][1] * inv0);
            *(float2*)(cp1 + col) = make_float2(oacc[mt][nt][2] * inv1, oacc[mt][nt][3] * inv1);
        }
    }
}

// ---------------- launch ----------------
extern "C" void kernel_launch(void* const* d_in, const int* in_sizes, int n_in,
                              void* d_out, int out_size)
{
    const float* x     = (const float*)d_in[0];
    const float* fcos  = (const float*)d_in[1];
    const float* fsin  = (const float*)d_in[2];
    // d_in[3] = mask (causal; handled analytically)
    const float* wq_a  = (const float*)d_in[4];
    const float* q_ln  = (const float*)d_in[5];
    const float* wq_b  = (const float*)d_in[6];
    const float* wkv_a = (const float*)d_in[7];
    const float* kv_ln = (const float*)d_in[8];
    const float* wkv_b = (const float*)d_in[9];
    const float* wo    = (const float*)d_in[10];
    float* out = (float*)d_out;

    float *qlat, *q, *kv, *kfull, *qfull, *ctx, *attnout, *wkvbT;
    cudaGetSymbolAddress((void**)&qlat,    g_qlat);
    cudaGetSymbolAddress((void**)&q,       g_q);
    cudaGetSymbolAddress((void**)&kv,      g_kv);
    cudaGetSymbolAddress((void**)&kfull,   g_kfull);
    cudaGetSymbolAddress((void**)&qfull,   g_qfull);
    cudaGetSymbolAddress((void**)&ctx,     g_ctx);
    cudaGetSymbolAddress((void**)&attnout, g_attnout);
    cudaGetSymbolAddress((void**)&wkvbT,   g_wkvbT);

    cudaFuncSetAttribute(attn_kernel, cudaFuncAttributeMaxDynamicSharedMemorySize,
                         ATTN_SMEM_BYTES);

    dim3 blk(256);

    // 0. transpose wkv_b nope half -> wkvbT[h][512][128]
    transpose_wkvb_kernel<<<dim3(KVLORA / 32, NOPEc / 32, Hh), blk>>>(wkv_b, wkvbT);

    // 1. q_lat_pre = x @ wq_a^T      (4096 x 1536, K=2048)
    gemm_tc_kernel<0><<<dim3(QLORA / 128, ROWS / 128, 1), blk>>>(
        x, DIMc, 0, wq_a, DIMc, 0, qlat, QLORA, 0, ROWS, QLORA, DIMc);

    // 2. rmsnorm in place
    rmsnorm_kernel<<<ROWS, 256>>>(qlat, q_ln, QLORA);

    // 3. q = q_lat @ wq_b^T          (4096 x 3072, K=1536)
    gemm_tc_kernel<0><<<dim3((Hh * QKH) / 128, ROWS / 128, 1), blk>>>(
        qlat, QLORA, 0, wq_b, QLORA, 0, q, Hh * QKH, 0, ROWS, Hh * QKH, QLORA);

    // 4. kv = x @ wkv_a^T            (4096 x 576, K=2048)
    gemm_tc_kernel<0><<<dim3((DF + 127) / 128, ROWS / 128, 1), blk>>>(
        x, DIMc, 0, wkv_a, DIMc, 0, kv, DF, 0, ROWS, DF, DIMc);

    // 5. kfull = [rmsnorm(kv_lat), rope(k_pe)]  (tf32-rounded)
    kvprep_kernel<<<ROWS, 256>>>(kv, kv_ln, fcos, fsin, kfull);

    // 6. q-absorb per head: qfull[:, h, :512] = q_nope_h @ wkvbT[h]^T (rounded epilogue)
    gemm_tc_kernel<1><<<dim3(KVLORA / 128, ROWS / 128, Hh), blk>>>(
        q, Hh * QKH, QKH,
        wkvbT, NOPEc, (long)KVLORA * NOPEc,
        qfull, Hh * DF, DF,
        ROWS, KVLORA, NOPEc);

    // 7. qfull[:, h, 512:576] = rope(q_pe)  (tf32-rounded)
    ropeq_kernel<<<ROWS, 512>>>(q, fcos, fsin, qfull);

    // 8. flash attention -> ctx (B,S,H,512)
    attn_kernel<<<dim3(Ss / 32, Bb * Hh), 256, ATTN_SMEM_BYTES>>>(qfull, kfull, ctx);

    // 9. per-head out-proj: attnout[:, h*128:(h+1)*128] = ctx_h @ wkv_b3[h, 128:256, :]^T
    gemm_tc_kernel<0><<<dim3(1, ROWS / 128, Hh), blk>>>(
        ctx, Hh * KVLORA, KVLORA,
        wkv_b + (size_t)NOPEc * KVLORA, KVLORA, (long)(NOPEc + VDIMc) * KVLORA,
        attnout, DIMc, VDIMc,
        ROWS, VDIMc, KVLORA);

    // 10. out = attnout @ wo^T       (4096 x 2048, K=2048)
    gemm_tc_kernel<0><<<dim3(DIMc / 128, ROWS / 128, 1), blk>>>(
        attnout, DIMc, 0, wo, DIMc, 0, out, DIMc, 0, ROWS, DIMc, DIMc);
}

// round 13
// speedup vs baseline: 1.1115x; 1.1115x over previous
#include <cuda_runtime.h>
#include <math.h>
#include <stdint.h>

// ---------------- problem constants ----------------
#define Bb     2
#define Ss     2048
#define DIMc   2048
#define Hh     16
#define QLORA  1536
#define KVLORA 512
#define NOPEc  128
#define ROPEc  64
#define VDIMc  128
#define QKH    192            // NOPE + ROPE
#define ROWS   (Bb*Ss)        // 4096
#define DF     576            // 512 latent + 64 rope
#define SCALEc 0.07216878364870322f  // 1/sqrt(192)
#define EPSc   1e-6f

// ---------------- scratch (static device arrays; no allocation) ----------------
__device__ float g_qlat[(size_t)ROWS * QLORA];          // 4096 x 1536 (tf32 after rmsnorm)
__device__ float g_q[(size_t)ROWS * (Hh * QKH)];        // 4096 x 3072 (tf32)
__device__ float g_kv[(size_t)ROWS * DF];               // 4096 x 576  (fp32)
__device__ float g_kfull[(size_t)ROWS * DF];            // 4096 x 576  (tf32)
__device__ float g_qfull[(size_t)ROWS * Hh * DF];       // 4096 x 16 x 576 (tf32)
__device__ float g_ctx[(size_t)ROWS * Hh * KVLORA];     // 4096 x 16 x 512 (tf32)
__device__ float g_attnout[(size_t)ROWS * DIMc];        // 4096 x 2048 (tf32)
__device__ float g_wkvbT[(size_t)Hh * KVLORA * NOPEc];  // 16 x 512 x 128 (tf32, transposed nope)
__device__ float g_wkvbV[(size_t)Hh * VDIMc * KVLORA];  // 16 x 128 x 512 (tf32, v half)
__device__ float g_xr[(size_t)ROWS * DIMc];             // tf32 copy of x
__device__ float g_wqa_r[(size_t)QLORA * DIMc];         // tf32 weights
__device__ float g_wqb_r[(size_t)(Hh * QKH) * QLORA];
__device__ float g_wkva_r[(size_t)DF * DIMc];
__device__ float g_wo_r[(size_t)DIMc * DIMc];

// ================= tf32 helpers =================
__device__ __forceinline__ uint32_t f2tf(float x) {
    uint32_t r;
    asm("cvt.rna.tf32.f32 %0, %1;" : "=r"(r) : "f"(x));
    return r;
}
__device__ __forceinline__ float f2tf_f(float x) { return __uint_as_float(f2tf(x)); }
__device__ __forceinline__ void mma_tf32(float* d, const uint32_t* a, const uint32_t* b) {
    asm volatile(
        "mma.sync.aligned.m16n8k8.row.col.f32.tf32.tf32.f32 "
        "{%0,%1,%2,%3}, {%4,%5,%6,%7}, {%8,%9}, {%0,%1,%2,%3};"
        : "+f"(d[0]), "+f"(d[1]), "+f"(d[2]), "+f"(d[3])
        : "r"(a[0]), "r"(a[1]), "r"(a[2]), "r"(a[3]), "r"(b[0]), "r"(b[1]));
}
__device__ __forceinline__ uint32_t smem_u32(const void* p) {
    uint32_t a;
    asm("{ .reg .u64 t; cvta.to.shared.u64 t, %1; cvt.u32.u64 %0, t; }" : "=r"(a) : "l"(p));
    return a;
}
__device__ __forceinline__ void cpa16(uint32_t dst, const void* src) {
    asm volatile("cp.async.cg.shared.global [%0], [%1], 16;" :: "r"(dst), "l"(src));
}
__device__ __forceinline__ void cpa16z(uint32_t dst, const void* src, uint32_t sz) {
    asm volatile("cp.async.cg.shared.global [%0], [%1], 16, %2;" :: "r"(dst), "l"(src), "r"(sz));
}

// ---------------- elementwise tf32 round (float4) ----------------
__global__ __launch_bounds__(256) void round4_kernel(
    const float4* __restrict__ src, float4* __restrict__ dst, int n4)
{
    int i = blockIdx.x * 256 + threadIdx.x;
    if (i < n4) {
        float4 v = src[i];
        v.x = f2tf_f(v.x); v.y = f2tf_f(v.y);
        v.z = f2tf_f(v.z); v.w = f2tf_f(v.w);
        dst[i] = v;
    }
}

// ---------------- wkv_b v-half -> rounded contiguous copy [h][128][512] ----------------
__global__ __launch_bounds__(256) void wkvbv_kernel(
    const float* __restrict__ w, float* __restrict__ out)
{
    int i = blockIdx.x * 256 + threadIdx.x;          // over 16*128*512/4 float4
    int n4 = Hh * VDIMc * KVLORA / 4;
    if (i < n4) {
        int h = i / (VDIMc * KVLORA / 4);
        int rem = i - h * (VDIMc * KVLORA / 4);
        const float4* src = (const float4*)(w + ((size_t)h * (NOPEc + VDIMc) + NOPEc) * KVLORA);
        float4 v = src[rem];
        v.x = f2tf_f(v.x); v.y = f2tf_f(v.y);
        v.z = f2tf_f(v.z); v.w = f2tf_f(v.w);
        ((float4*)(out + (size_t)h * VDIMc * KVLORA))[rem] = v;
    }
}

// ================= tf32 tensor-core GEMM (TB: C = A @ B^T) =================
// Inputs A,B MUST be pre-rounded to tf32. 256 threads, 8 warps (2x4),
// 128x128 block tile, BK=16, warp tile 64x32.
// 4-stage cp.async pipeline: global -> swizzled smem directly (no reg staging,
// no cvt, no STS). One __syncthreads per k-tile.
// Smem swizzle: word(m,k) = m*16 + (k ^ ((m>>1)&3)*4)  (16B-unit XOR; cp.async-safe).
#define GSMEM (16384 * 4)   // 4 stages x (A 8KB + B 8KB) = 64KB

template<int ROUND>
__global__ __launch_bounds__(256) void gemm_tc_kernel(
    const float* __restrict__ A, int lda, long sA_,
    const float* __restrict__ B, int ldb, long sB_,
    float* __restrict__ C, int ldc, long sC_,
    int M, int N, int K)
{
    extern __shared__ __align__(16) uint32_t dsm[];   // [4][2048] A then [4][2048] B

    int z = blockIdx.z;
    A += (size_t)z * sA_;
    B += (size_t)z * sB_;
    C += (size_t)z * sC_;

    const int tid    = threadIdx.x;
    const int lane   = tid & 31;
    const int warp   = tid >> 5;
    const int warp_m = warp >> 2;      // 0..1
    const int warp_n = warp & 3;       // 0..3
    const int g = lane >> 2, t = lane & 3;
    const int m0 = blockIdx.y * 128;
    const int n0 = blockIdx.x * 128;
    const int KT = K >> 4;

    float acc[4][4][4];
#pragma unroll
    for (int mt = 0; mt < 4; mt++)
#pragma unroll
        for (int nt = 0; nt < 4; nt++)
#pragma unroll
            for (int e = 0; e < 4; e++) acc[mt][nt][e] = 0.f;

    const int lr0 = tid >> 2;          // row 0..63 (pass 0), +64 (pass 1)
    const int lkc = (tid & 3) << 2;    // k word offset 0/4/8/12
    const uint32_t smem_base = smem_u32(dsm);

    auto load_stage = [&](int chunk, int s) {
        int k0 = chunk << 4;
        uint32_t abase = smem_base + (uint32_t)s * 8192;
        uint32_t bbase = abase + 32768;
#pragma unroll
        for (int i = 0; i < 2; i++) {
            int r = lr0 + i * 64;
            uint32_t off = (uint32_t)(r * 16 + (lkc ^ (((r >> 1) & 3) << 2))) * 4;
            cpa16(abase + off, A + (size_t)(m0 + r) * lda + k0 + lkc);
            cpa16z(bbase + off, B + (size_t)(n0 + r) * ldb + k0 + lkc,
                   (n0 + r < N) ? 16u : 0u);
        }
    };

    const int fr = (g >> 1) << 2;      // fragment-row swizzle

    auto compute = [&](int s) {
        const uint32_t* As = dsm + (uint32_t)s * 2048;
        const uint32_t* Bs = As + 8192;
#pragma unroll
        for (int ks = 0; ks < 2; ks++) {
            const int xk  = ((ks << 3) | t) ^ fr;
            const int xk2 = xk ^ 4;
            uint32_t af[4][4];
            uint32_t bf[4][2];
#pragma unroll
            for (int mt = 0; mt < 4; mt++) {
                int base = (warp_m * 64 + mt * 16 + g) * 16;
                af[mt][0] = As[base + xk];
                af[mt][1] = As[base + 128 + xk];
                af[mt][2] = As[base + xk2];
                af[mt][3] = As[base + 128 + xk2];
            }
#pragma unroll
            for (int nt = 0; nt < 4; nt++) {
                int base = (warp_n * 32 + nt * 8 + g) * 16;
                bf[nt][0] = Bs[base + xk];
                bf[nt][1] = Bs[base + xk2];
            }
#pragma unroll
            for (int mt = 0; mt < 4; mt++)
#pragma unroll
                for (int nt = 0; nt < 4; nt++)
                    mma_tf32(acc[mt][nt], af[mt], bf[nt]);
        }
    };

    // prologue: stages 0..2
    const int PRE = (KT < 3) ? KT : 3;
    for (int s = 0; s < PRE; s++) {
        load_stage(s, s);
        asm volatile("cp.async.commit_group;" ::: "memory");
    }

    for (int kt = 0; kt < KT; kt++) {
        asm volatile("cp.async.wait_group 2;" ::: "memory");
        __syncthreads();
        if (kt + 3 < KT) load_stage(kt + 3, (kt + 3) & 3);
        asm volatile("cp.async.commit_group;" ::: "memory");
        compute(kt & 3);
    }

    // ---- epilogue ----
#pragma unroll
    for (int mt = 0; mt < 4; mt++) {
        int row0 = m0 + warp_m * 64 + mt * 16 + g;
#pragma unroll
        for (int nt = 0; nt < 4; nt++) {
            int col = n0 + warp_n * 32 + nt * 8 + 2 * t;
            if (col < N) {
                float2 v0, v1;
                if (ROUND) {
                    v0 = make_float2(f2tf_f(acc[mt][nt][0]), f2tf_f(acc[mt][nt][1]));
                    v1 = make_float2(f2tf_f(acc[mt][nt][2]), f2tf_f(acc[mt][nt][3]));
                } else {
                    v0 = make_float2(acc[mt][nt][0], acc[mt][nt][1]);
                    v1 = make_float2(acc[mt][nt][2], acc[mt][nt][3]);
                }
                *(float2*)(C + (size_t)row0 * ldc + col) = v0;
                *(float2*)(C + (size_t)(row0 + 8) * ldc + col) = v1;
            }
        }
    }
}

// ---------------- transpose wkv_b nope half (tf32-rounded): out[h][c][d] ----------------
__global__ __launch_bounds__(256) void transpose_wkvb_kernel(
    const float* __restrict__ w, float* __restrict__ out)
{
    __shared__ float tile[32][33];
    int h = blockIdx.z;
    int c0 = blockIdx.x * 32;
    int d0 = blockIdx.y * 32;
    int tx = threadIdx.x & 31, ty = threadIdx.x >> 5;
#pragma unroll
    for (int i = ty; i < 32; i += 8)
        tile[i][tx] = w[((size_t)h * 256 + d0 + i) * KVLORA + c0 + tx];
    __syncthreads();
#pragma unroll
    for (int i = ty; i < 32; i += 8)
        out[((size_t)h * KVLORA + c0 + i) * NOPEc + d0 + tx] = f2tf_f(tile[tx][i]);
}

// ---------------- RMSNorm (in-place, tf32-rounded output) ----------------
__global__ __launch_bounds__(256) void rmsnorm_kernel(
    float* __restrict__ x, const float* __restrict__ w, int L)
{
    __shared__ float sbuf[8];
    int row = blockIdx.x;
    float* xr = x + (size_t)row * L;
    float ss = 0.f;
    for (int i = threadIdx.x; i < L; i += 256) { float v = xr[i]; ss += v * v; }
#pragma unroll
    for (int o = 16; o; o >>= 1) ss += __shfl_xor_sync(0xffffffffu, ss, o);
    int warp = threadIdx.x >> 5, lane = threadIdx.x & 31;
    if (lane == 0) sbuf[warp] = ss;
    __syncthreads();
    if (threadIdx.x == 0) {
        float t = 0.f;
#pragma unroll
        for (int i = 0; i < 8; i++) t += sbuf[i];
        sbuf[0] = rsqrtf(t / (float)L + EPSc);
    }
    __syncthreads();
    float sc = sbuf[0];
    for (int i = threadIdx.x; i < L; i += 256) xr[i] = f2tf_f(xr[i] * sc * w[i]);
}

// ---------------- kv split: rmsnorm(latent) + rope(k_pe) -> kfull (tf32) ----------------
__global__ __launch_bounds__(256) void kvprep_kernel(
    const float* __restrict__ kv, const float* __restrict__ w,
    const float* __restrict__ fcos, const float* __restrict__ fsin,
    float* __restrict__ kfull)
{
    __shared__ float sbuf[8];
    int row = blockIdx.x;
    int s = row & (Ss - 1);
    const float* kr = kv + (size_t)row * DF;
    float* kf = kfull + (size_t)row * DF;

    float ss = 0.f;
    for (int i = threadIdx.x; i < KVLORA; i += 256) { float v = kr[i]; ss += v * v; }
#pragma unroll
    for (int o = 16; o; o >>= 1) ss += __shfl_xor_sync(0xffffffffu, ss, o);
    int warp = threadIdx.x >> 5, lane = threadIdx.x & 31;
    if (lane == 0) sbuf[warp] = ss;
    __syncthreads();
    if (threadIdx.x == 0) {
        float t = 0.f;
#pragma unroll
        for (int i = 0; i < 8; i++) t += sbuf[i];
        sbuf[0] = rsqrtf(t / (float)KVLORA + EPSc);
    }
    __syncthreads();
    float sc = sbuf[0];
    for (int i = threadIdx.x; i < KVLORA; i += 256) kf[i] = f2tf_f(kr[i] * sc * w[i]);

    if (threadIdx.x < 32) {
        int i = threadIdx.x;
        float x0 = kr[KVLORA + 2 * i], x1 = kr[KVLORA + 2 * i + 1];
        float c = fcos[s * 32 + i], sn = fsin[s * 32 + i];
        kf[KVLORA + 2 * i]     = f2tf_f(x0 * c - x1 * sn);
        kf[KVLORA + 2 * i + 1] = f2tf_f(x0 * sn + x1 * c);
    }
}

// ---------------- rope(q_pe) -> qfull[:, :, 512:576] (tf32) ----------------
__global__ __launch_bounds__(512) void ropeq_kernel(
    const float* __restrict__ q, const float* __restrict__ fcos,
    const float* __restrict__ fsin, float* __restrict__ qfull)
{
    int row = blockIdx.x;
    int s = row & (Ss - 1);
    int t = threadIdx.x;       // 512 = 16 heads * 32 pairs
    int h = t >> 5, i = t & 31;
    const float* qr = q + (size_t)row * (Hh * QKH) + h * QKH + NOPEc;
    float x0 = qr[2 * i], x1 = qr[2 * i + 1];
    float c = fcos[s * 32 + i], sn = fsin[s * 32 + i];
    float* dst = qfull + ((size_t)row * Hh + h) * DF + KVLORA;
    dst[2 * i]     = f2tf_f(x0 * c - x1 * sn);
    dst[2 * i + 1] = f2tf_f(x0 * sn + x1 * c);
}

// ---------------- flash attention (tf32 mma, 32q x 32k tiles, 4-way k-split) ----------------
// Inputs qfull/kfull pre-rounded tf32; tile loads are raw cp.async copies.
// ctx output is tf32-rounded (feeds out-proj GEMM).
#define KSTR 588
#define PSTR 36
#define ATTN_SMEM_BYTES ((2 * 32 * KSTR + 4 * 32 * PSTR + 64) * 4)

__global__ __launch_bounds__(256, 1) void attn_kernel(
    const float* __restrict__ qfull, const float* __restrict__ kfull,
    float* __restrict__ ctx)
{
    extern __shared__ float sm[];
    float* Qs   = sm;                   // 32 x 588
    float* Ks   = sm + 32 * KSTR;       // 32 x 588 (cols 0..511 double as V)
    float* Ps   = Ks + 32 * KSTR;       // 4 x (32 x 36)
    float* arow = Ps + 4 * 32 * PSTR;   // 32
    float* lrow = arow + 32;            // 32

    const int tid  = threadIdx.x;
    const int lane = tid & 31, warp = tid >> 5;
    const int g = lane >> 2, t = lane & 3;
    const int wk = warp & 3, wm = warp >> 2;
    const int bh = blockIdx.y;
    const int b = bh >> 4, h = bh & 15;
    const int s0 = blockIdx.x * 32;

    const int trow = tid >> 3, t8 = tid & 7;
    const uint32_t qdst = smem_u32(Qs) + ((uint32_t)trow * KSTR + (uint32_t)t8 * 4) * 4;
    const uint32_t kdst = smem_u32(Ks) + ((uint32_t)trow * KSTR + (uint32_t)t8 * 4) * 4;

    {
        const float4* src = (const float4*)(qfull + ((size_t)(b * Ss + s0 + trow) * Hh + h) * DF) + t8;
#pragma unroll
        for (int c = 0; c < 18; c++) cpa16(qdst + c * 128, src + c * 8);
        asm volatile("cp.async.commit_group;" ::: "memory");
    }

    float oacc[2][8][4];
#pragma unroll
    for (int mt = 0; mt < 2; mt++)
#pragma unroll
        for (int nt = 0; nt < 8; nt++)
#pragma unroll
            for (int e = 0; e < 4; e++) oacc[mt][nt][e] = 0.f;

    float mreg[4], lreg[4];
#pragma unroll
    for (int ii = 0; ii < 4; ii++) { mreg[ii] = -INFINITY; lreg[ii] = 0.f; }

    const int ntiles = s0 / 32 + 1;
    for (int kt = 0; kt < ntiles; kt++) {
        int t0 = kt * 32;
        {
            const float4* src = (const float4*)(kfull + (size_t)(b * Ss + t0 + trow) * DF) + t8;
#pragma unroll
            for (int c = 0; c < 18; c++) cpa16(kdst + c * 128, src + c * 8);
            asm volatile("cp.async.commit_group;" ::: "memory");
            asm volatile("cp.async.wait_group 0;" ::: "memory");
        }
        __syncthreads();

        // ---- scores: warp (wm, wk) -> m16 x n32 tile, k-quarter wk ----
        {
            float sacc[4][4];
#pragma unroll
            for (int nt = 0; nt < 4; nt++)
#pragma unroll
                for (int e = 0; e < 4; e++) sacc[nt][e] = 0.f;

            const float* qb0 = Qs + (wm * 16 + g) * KSTR + wk * 144 + t;
#pragma unroll 3
            for (int ks = 0; ks < 18; ks++) {
                const float* qb = qb0 + ks * 8;
                uint32_t a[4];
                a[0] = __float_as_uint(qb[0]);
                a[1] = __float_as_uint(qb[8 * KSTR]);
                a[2] = __float_as_uint(qb[4]);
                a[3] = __float_as_uint(qb[8 * KSTR + 4]);
#pragma unroll
                for (int nt = 0; nt < 4; nt++) {
                    const float* kb = Ks + (nt * 8 + g) * KSTR + wk * 144 + ks * 8 + t;
                    uint32_t bf[2];
                    bf[0] = __float_as_uint(kb[0]);
                    bf[1] = __float_as_uint(kb[4]);
                    mma_tf32(sacc[nt], a, bf);
                }
            }
            float* Pw = Ps + wk * 32 * PSTR;
#pragma unroll
            for (int nt = 0; nt < 4; nt++) {
                int colb = nt * 8 + 2 * t;
                *(float2*)&Pw[(wm * 16 + g) * PSTR + colb] =
                    make_float2(sacc[nt][0], sacc[nt][1]);
                *(float2*)&Pw[(wm * 16 + g + 8) * PSTR + colb] =
                    make_float2(sacc[nt][2], sacc[nt][3]);
            }
        }
        __syncthreads();

        // ---- softmax ----
        {
#pragma unroll
            for (int ii = 0; ii < 4; ii++) {
                int i = warp * 4 + ii;
                float v = (Ps[i * PSTR + lane] +
                           Ps[32 * PSTR + i * PSTR + lane] +
                           Ps[64 * PSTR + i * PSTR + lane] +
                           Ps[96 * PSTR + i * PSTR + lane]) * SCALEc;
                if (t0 + lane > s0 + i) v = -INFINITY;
                float mx = v;
#pragma unroll
                for (int o = 16; o; o >>= 1) mx = fmaxf(mx, __shfl_xor_sync(0xffffffffu, mx, o));
                float mnew = fmaxf(mreg[ii], mx);
                float p = __expf(v - mnew);
                float psum = p;
#pragma unroll
                for (int o = 16; o; o >>= 1) psum += __shfl_xor_sync(0xffffffffu, psum, o);
                float al = __expf(mreg[ii] - mnew);
                lreg[ii] = lreg[ii] * al + psum;
                mreg[ii] = mnew;
                Ps[i * PSTR + lane] = f2tf_f(p);
                if (lane == 0) arow[i] = al;
            }
        }
        __syncthreads();

        // ---- PV ----
        {
#pragma unroll
            for (int mt = 0; mt < 2; mt++) {
                float al0 = arow[mt * 16 + g];
                float al1 = arow[mt * 16 + g + 8];
#pragma unroll
                for (int nt = 0; nt < 8; nt++) {
                    oacc[mt][nt][0] *= al0; oacc[mt][nt][1] *= al0;
                    oacc[mt][nt][2] *= al1; oacc[mt][nt][3] *= al1;
                }
            }
#pragma unroll
            for (int jb = 0; jb < 4; jb++) {
                int j0 = jb * 8;
                uint32_t pa[2][4];
#pragma unroll
                for (int mt = 0; mt < 2; mt++) {
                    const float* pb = Ps + (mt * 16 + g) * PSTR + j0 + t;
                    pa[mt][0] = __float_as_uint(pb[0]);
                    pa[mt][1] = __float_as_uint(pb[8 * PSTR]);
                    pa[mt][2] = __float_as_uint(pb[4]);
                    pa[mt][3] = __float_as_uint(pb[8 * PSTR + 4]);
                }
#pragma unroll
                for (int nt = 0; nt < 8; nt++) {
                    const float* vbp = Ks + (j0 + t) * KSTR + warp * 64 + nt * 8 + g;
                    uint32_t vb[2];
                    vb[0] = __float_as_uint(vbp[0]);
                    vb[1] = __float_as_uint(vbp[4 * KSTR]);
                    mma_tf32(oacc[0][nt], pa[0], vb);
                    mma_tf32(oacc[1][nt], pa[1], vb);
                }
            }
        }
        __syncthreads();
    }

    // ---- publish l, normalize, store ctx (tf32-rounded) ----
    if (lane == 0) {
#pragma unroll
        for (int ii = 0; ii < 4; ii++) lrow[warp * 4 + ii] = lreg[ii];
    }
    __syncthreads();
#pragma unroll
    for (int mt = 0; mt < 2; mt++) {
        int r0 = mt * 16 + g;
        int r1 = mt * 16 + g + 8;
        float inv0 = 1.0f / lrow[r0];
        float inv1 = 1.0f / lrow[r1];
        float* cp0 = ctx + ((size_t)(b * Ss + s0 + r0) * Hh + h) * KVLORA + warp * 64;
        float* cp1 = ctx + ((size_t)(b * Ss + s0 + r1) * Hh + h) * KVLORA + warp * 64;
#pragma unroll
        for (int nt = 0; nt < 8; nt++) {
            int col = nt * 8 + 2 * t;
            *(float2*)(cp0 + col) =
                make_float2(f2tf_f(oacc[mt][nt][0] * inv0), f2tf_f(oacc[mt][nt][1] * inv0));
            *(float2*)(cp1 + col) =
                make_float2(f2tf_f(oacc[mt][nt][2] * inv1), f2tf_f(oacc[mt][nt][3] * inv1));
        }
    }
}

// ---------------- launch ----------------
extern "C" void kernel_launch(void* const* d_in, const int* in_sizes, int n_in,
                              void* d_out, int out_size)
{
    const float* x     = (const float*)d_in[0];
    const float* fcos  = (const float*)d_in[1];
    const float* fsin  = (const float*)d_in[2];
    // d_in[3] = mask (causal; handled analytically)
    const float* wq_a  = (const float*)d_in[4];
    const float* q_ln  = (const float*)d_in[5];
    const float* wq_b  = (const float*)d_in[6];
    const float* wkv_a = (const float*)d_in[7];
    const float* kv_ln = (const float*)d_in[8];
    const float* wkv_b = (const float*)d_in[9];
    const float* wo    = (const float*)d_in[10];
    float* out = (float*)d_out;

    float *qlat, *q, *kv, *kfull, *qfull, *ctx, *attnout, *wkvbT, *wkvbV;
    float *xr, *wqa_r, *wqb_r, *wkva_r, *wo_r;
    cudaGetSymbolAddress((void**)&qlat,    g_qlat);
    cudaGetSymbolAddress((void**)&q,       g_q);
    cudaGetSymbolAddress((void**)&kv,      g_kv);
    cudaGetSymbolAddress((void**)&kfull,   g_kfull);
    cudaGetSymbolAddress((void**)&qfull,   g_qfull);
    cudaGetSymbolAddress((void**)&ctx,     g_ctx);
    cudaGetSymbolAddress((void**)&attnout, g_attnout);
    cudaGetSymbolAddress((void**)&wkvbT,   g_wkvbT);
    cudaGetSymbolAddress((void**)&wkvbV,   g_wkvbV);
    cudaGetSymbolAddress((void**)&xr,      g_xr);
    cudaGetSymbolAddress((void**)&wqa_r,   g_wqa_r);
    cudaGetSymbolAddress((void**)&wqb_r,   g_wqb_r);
    cudaGetSymbolAddress((void**)&wkva_r,  g_wkva_r);
    cudaGetSymbolAddress((void**)&wo_r,    g_wo_r);

    cudaFuncSetAttribute(gemm_tc_kernel<0>, cudaFuncAttributeMaxDynamicSharedMemorySize, GSMEM);
    cudaFuncSetAttribute(gemm_tc_kernel<1>, cudaFuncAttributeMaxDynamicSharedMemorySize, GSMEM);
    cudaFuncSetAttribute(attn_kernel, cudaFuncAttributeMaxDynamicSharedMemorySize,
                         ATTN_SMEM_BYTES);

    dim3 blk(256);

    // 0a. pre-round inputs to tf32
    auto round_n = [&](const float* s, float* d, size_t n) {
        int n4 = (int)(n / 4);
        round4_kernel<<<(n4 + 255) / 256, blk>>>((const float4*)s, (float4*)d, n4);
    };
    round_n(x,     xr,     (size_t)ROWS * DIMc);
    round_n(wq_a,  wqa_r,  (size_t)QLORA * DIMc);
    round_n(wq_b,  wqb_r,  (size_t)(Hh * QKH) * QLORA);
    round_n(wkv_a, wkva_r, (size_t)DF * DIMc);
    round_n(wo,    wo_r,   (size_t)DIMc * DIMc);
    wkvbv_kernel<<<(Hh * VDIMc * KVLORA / 4 + 255) / 256, blk>>>(wkv_b, wkvbV);

    // 0b. transpose wkv_b nope half -> wkvbT[h][512][128] (rounded)
    transpose_wkvb_kernel<<<dim3(KVLORA / 32, NOPEc / 32, Hh), blk>>>(wkv_b, wkvbT);

    // 1. q_lat_pre = xr @ wqa_r^T      (4096 x 1536, K=2048)
    gemm_tc_kernel<0><<<dim3(QLORA / 128, ROWS / 128, 1), blk, GSMEM>>>(
        xr, DIMc, 0, wqa_r, DIMc, 0, qlat, QLORA, 0, ROWS, QLORA, DIMc);

    // 2. rmsnorm in place (tf32-rounded output)
    rmsnorm_kernel<<<ROWS, 256>>>(qlat, q_ln, QLORA);

    // 3. q = qlat @ wqb_r^T            (4096 x 3072, K=1536), rounded output
    gemm_tc_kernel<1><<<dim3((Hh * QKH) / 128, ROWS / 128, 1), blk, GSMEM>>>(
        qlat, QLORA, 0, wqb_r, QLORA, 0, q, Hh * QKH, 0, ROWS, Hh * QKH, QLORA);

    // 4. kv = xr @ wkva_r^T            (4096 x 576, K=2048), fp32 output
    gemm_tc_kernel<0><<<dim3((DF + 127) / 128, ROWS / 128, 1), blk, GSMEM>>>(
        xr, DIMc, 0, wkva_r, DIMc, 0, kv, DF, 0, ROWS, DF, DIMc);

    // 5. kfull = [rmsnorm(kv_lat), rope(k_pe)]  (tf32)
    kvprep_kernel<<<ROWS, 256>>>(kv, kv_ln, fcos, fsin, kfull);

    // 6. q-absorb per head: qfull[:, h, :512] = q_nope_h @ wkvbT[h]^T, rounded output
    gemm_tc_kernel<1><<<dim3(KVLORA / 128, ROWS / 128, Hh), blk, GSMEM>>>(
        q, Hh * QKH, QKH,
        wkvbT, NOPEc, (long)KVLORA * NOPEc,
        qfull, Hh * DF, DF,
        ROWS, KVLORA, NOPEc);

    // 7. qfull[:, h, 512:576] = rope(q_pe)  (tf32)
    ropeq_kernel<<<ROWS, 512>>>(q, fcos, fsin, qfull);

    // 8. flash attention -> ctx (tf32)
    attn_kernel<<<dim3(Ss / 32, Bb * Hh), 256, ATTN_SMEM_BYTES>>>(qfull, kfull, ctx);

    // 9. per-head out-proj: attnout = ctx_h @ wkvbV[h]^T, rounded output
    gemm_tc_kernel<1><<<dim3(1, ROWS / 128, Hh), blk, GSMEM>>>(
        ctx, Hh * KVLORA, KVLORA,
        wkvbV, KVLORA, (long)VDIMc * KVLORA,
        attnout, DIMc, VDIMc,
        ROWS, VDIMc, KVLORA);

    // 10. out = attnout @ wo_r^T       (4096 x 2048, K=2048), fp32 output
    gemm_tc_kernel<0><<<dim3(DIMc / 128, ROWS / 128, 1), blk, GSMEM>>>(
        attnout, DIMc, 0, wo_r, DIMc, 0, out, DIMc, 0, ROWS, DIMc, DIMc);
}

// round 14
// speedup vs baseline: 1.3093x; 1.1779x over previous
#include <cuda_runtime.h>
#include <cuda_fp16.h>
#include <math.h>
#include <stdint.h>

// ---------------- problem constants ----------------
#define Bb     2
#define Ss     2048
#define DIMc   2048
#define Hh     16
#define QLORA  1536
#define KVLORA 512
#define NOPEc  128
#define ROPEc  64
#define VDIMc  128
#define QKH    192            // NOPE + ROPE
#define ROWS   (Bb*Ss)        // 4096
#define DF     576            // 512 latent + 64 rope
#define SCALEc 0.07216878364870322f  // 1/sqrt(192)
#define EPSc   1e-6f

// ---------------- scratch (static device arrays; no allocation) ----------------
__device__ __half g_xh[(size_t)ROWS * DIMc];             // fp16 copy of x
__device__ __half g_wqa_h[(size_t)QLORA * DIMc];
__device__ __half g_wqb_h[(size_t)(Hh * QKH) * QLORA];
__device__ __half g_wkva_h[(size_t)DF * DIMc];
__device__ __half g_wo_h[(size_t)DIMc * DIMc];
__device__ float  g_qlat[(size_t)ROWS * QLORA];          // fp32 (pre-rmsnorm)
__device__ __half g_qlat_h[(size_t)ROWS * QLORA];        // fp16 (post-rmsnorm)
__device__ __half g_q[(size_t)ROWS * (Hh * QKH)];        // fp16
__device__ float  g_kv[(size_t)ROWS * DF];               // fp32
__device__ float  g_kfull[(size_t)ROWS * DF];            // tf32 (attention operand)
__device__ float  g_qfull[(size_t)ROWS * Hh * DF];       // tf32 (attention operand)
__device__ __half g_ctx[(size_t)ROWS * Hh * KVLORA];     // fp16
__device__ __half g_attnout[(size_t)ROWS * DIMc];        // fp16
__device__ __half g_wkvbT[(size_t)Hh * KVLORA * NOPEc];  // fp16 transposed nope half
__device__ __half g_wkvbV[(size_t)Hh * VDIMc * KVLORA];  // fp16 v half

// ================= helpers =================
__device__ __forceinline__ uint32_t f2tf(float x) {
    uint32_t r;
    asm("cvt.rna.tf32.f32 %0, %1;" : "=r"(r) : "f"(x));
    return r;
}
__device__ __forceinline__ float f2tf_f(float x) { return __uint_as_float(f2tf(x)); }
__device__ __forceinline__ void mma_tf32(float* d, const uint32_t* a, const uint32_t* b) {
    asm volatile(
        "mma.sync.aligned.m16n8k8.row.col.f32.tf32.tf32.f32 "
        "{%0,%1,%2,%3}, {%4,%5,%6,%7}, {%8,%9}, {%0,%1,%2,%3};"
        : "+f"(d[0]), "+f"(d[1]), "+f"(d[2]), "+f"(d[3])
        : "r"(a[0]), "r"(a[1]), "r"(a[2]), "r"(a[3]), "r"(b[0]), "r"(b[1]));
}
__device__ __forceinline__ void mma_f16(float* d, const uint32_t* a, const uint32_t* b) {
    asm volatile(
        "mma.sync.aligned.m16n8k16.row.col.f32.f16.f16.f32 "
        "{%0,%1,%2,%3}, {%4,%5,%6,%7}, {%8,%9}, {%0,%1,%2,%3};"
        : "+f"(d[0]), "+f"(d[1]), "+f"(d[2]), "+f"(d[3])
        : "r"(a[0]), "r"(a[1]), "r"(a[2]), "r"(a[3]), "r"(b[0]), "r"(b[1]));
}
__device__ __forceinline__ uint32_t smem_u32(const void* p) {
    uint32_t a;
    asm("{ .reg .u64 t; cvta.to.shared.u64 t, %1; cvt.u32.u64 %0, t; }" : "=r"(a) : "l"(p));
    return a;
}
__device__ __forceinline__ void cpa16(uint32_t dst, const void* src) {
    asm volatile("cp.async.cg.shared.global [%0], [%1], 16;" :: "r"(dst), "l"(src));
}
__device__ __forceinline__ void cpa16z(uint32_t dst, const void* src, uint32_t sz) {
    asm volatile("cp.async.cg.shared.global [%0], [%1], 16, %2;" :: "r"(dst), "l"(src), "r"(sz));
}

// ---------------- bulk fp32 -> fp16 convert (8 elements/thread) ----------------
__global__ __launch_bounds__(256) void tohalf_kernel(
    const float4* __restrict__ src, uint4* __restrict__ dst, int n8)
{
    int i = blockIdx.x * 256 + threadIdx.x;
    if (i < n8) {
        float4 a = src[2 * i], b = src[2 * i + 1];
        __half2 h0 = __floats2half2_rn(a.x, a.y);
        __half2 h1 = __floats2half2_rn(a.z, a.w);
        __half2 h2 = __floats2half2_rn(b.x, b.y);
        __half2 h3 = __floats2half2_rn(b.z, b.w);
        uint4 o;
        o.x = *(uint32_t*)&h0; o.y = *(uint32_t*)&h1;
        o.z = *(uint32_t*)&h2; o.w = *(uint32_t*)&h3;
        dst[i] = o;
    }
}

// ---------------- wkv_b v-half -> fp16 contiguous copy [h][128][512] ----------------
__global__ __launch_bounds__(256) void wkvbv_kernel(
    const float* __restrict__ w, __half* __restrict__ out)
{
    int i = blockIdx.x * 256 + threadIdx.x;    // over 16*128*512/8 groups of 8
    int n8 = Hh * VDIMc * KVLORA / 8;
    if (i < n8) {
        int per_h = VDIMc * KVLORA / 8;        // 8192
        int h = i / per_h;
        int rem = i - h * per_h;
        const float4* src = (const float4*)(w + ((size_t)h * (NOPEc + VDIMc) + NOPEc) * KVLORA);
        float4 a = src[2 * rem], b = src[2 * rem + 1];
        __half2 h0 = __floats2half2_rn(a.x, a.y);
        __half2 h1 = __floats2half2_rn(a.z, a.w);
        __half2 h2 = __floats2half2_rn(b.x, b.y);
        __half2 h3 = __floats2half2_rn(b.z, b.w);
        uint4 o;
        o.x = *(uint32_t*)&h0; o.y = *(uint32_t*)&h1;
        o.z = *(uint32_t*)&h2; o.w = *(uint32_t*)&h3;
        ((uint4*)(out + (size_t)h * VDIMc * KVLORA))[rem] = o;
    }
}

// ================= fp16 tensor-core GEMM (TB: C = A @ B^T) =================
// A,B fp16 [.,K] row-major. 256 threads, 8 warps (2x4), 128x128 block tile,
// BK=32 halfs (16 4B-words/row), warp tile 64x32, m16n8k16 mma.
// 4-stage cp.async pipeline, one __syncthreads per k-tile.
// Smem swizzle (4B-word space): word(m,w) = m*16 + (w ^ ((m>>1)&3)*4).
// OUT: 0 = fp32 raw, 1 = fp32 tf32-rounded, 2 = fp16.
#define GSMEM (16384 * 4)   // 4 stages x (A 8KB + B 8KB)

template<int OUT>
__global__ __launch_bounds__(256) void gemm_f16_kernel(
    const __half* __restrict__ A, int lda, long sA_,
    const __half* __restrict__ B, int ldb, long sB_,
    void* __restrict__ Cv, int ldc, long sC_,
    int M, int N, int K)
{
    extern __shared__ __align__(16) uint32_t dsm[];

    int z = blockIdx.z;
    A += (size_t)z * sA_;
    B += (size_t)z * sB_;

    const int tid    = threadIdx.x;
    const int lane   = tid & 31;
    const int warp   = tid >> 5;
    const int warp_m = warp >> 2;      // 0..1
    const int warp_n = warp & 3;       // 0..3
    const int g = lane >> 2, t = lane & 3;
    const int m0 = blockIdx.y * 128;
    const int n0 = blockIdx.x * 128;
    const int KT = K >> 5;             // k-tiles of 32 halfs

    float acc[4][4][4];
#pragma unroll
    for (int mt = 0; mt < 4; mt++)
#pragma unroll
        for (int nt = 0; nt < 4; nt++)
#pragma unroll
            for (int e = 0; e < 4; e++) acc[mt][nt][e] = 0.f;

    const int lr0 = tid >> 2;          // row 0..63 (pass 0), +64 (pass 1)
    const int lkw = (tid & 3) << 2;    // word offset 0/4/8/12 (word = 2 halfs)
    const uint32_t smem_base = smem_u32(dsm);

    auto load_stage = [&](int chunk, int s) {
        int k0 = chunk << 5;           // half offset
        uint32_t abase = smem_base + (uint32_t)s * 8192;
        uint32_t bbase = abase + 32768;
#pragma unroll
        for (int i = 0; i < 2; i++) {
            int r = lr0 + i * 64;
            uint32_t off = (uint32_t)(r * 16 + (lkw ^ (((r >> 1) & 3) << 2))) * 4;
            cpa16(abase + off, A + (size_t)(m0 + r) * lda + k0 + lkw * 2);
            cpa16z(bbase + off, B + (size_t)(n0 + r) * ldb + k0 + lkw * 2,
                   (n0 + r < N) ? 16u : 0u);
        }
    };

    const int fr = (g >> 1) << 2;      // fragment-row swizzle

    auto compute = [&](int s) {
        const uint32_t* As = dsm + (uint32_t)s * 2048;
        const uint32_t* Bs = As + 8192;
#pragma unroll
        for (int ks = 0; ks < 2; ks++) {     // each kstep = 8 words = 16 halfs (one K16 mma)
            const int xk  = ((ks << 3) | t) ^ fr;
            const int xk2 = xk ^ 4;
            uint32_t af[4][4];
            uint32_t bf[4][2];
#pragma unroll
            for (int mt = 0; mt < 4; mt++) {
                int base = (warp_m * 64 + mt * 16 + g) * 16;
                af[mt][0] = As[base + xk];
                af[mt][1] = As[base + 128 + xk];
                af[mt][2] = As[base + xk2];
                af[mt][3] = As[base + 128 + xk2];
            }
#pragma unroll
            for (int nt = 0; nt < 4; nt++) {
                int base = (warp_n * 32 + nt * 8 + g) * 16;
                bf[nt][0] = Bs[base + xk];
                bf[nt][1] = Bs[base + xk2];
            }
#pragma unroll
            for (int mt = 0; mt < 4; mt++)
#pragma unroll
                for (int nt = 0; nt < 4; nt++)
                    mma_f16(acc[mt][nt], af[mt], bf[nt]);
        }
    };

    const int PRE = (KT < 3) ? KT : 3;
    for (int s = 0; s < PRE; s++) {
        load_stage(s, s);
        asm volatile("cp.async.commit_group;" ::: "memory");
    }

    for (int kt = 0; kt < KT; kt++) {
        asm volatile("cp.async.wait_group 2;" ::: "memory");
        __syncthreads();
        if (kt + 3 < KT) load_stage(kt + 3, (kt + 3) & 3);
        asm volatile("cp.async.commit_group;" ::: "memory");
        compute(kt & 3);
    }

    // ---- epilogue ----
#pragma unroll
    for (int mt = 0; mt < 4; mt++) {
        int row0 = m0 + warp_m * 64 + mt * 16 + g;
#pragma unroll
        for (int nt = 0; nt < 4; nt++) {
            int col = n0 + warp_n * 32 + nt * 8 + 2 * t;
            if (col < N) {
                if (OUT == 2) {
                    __half* C = (__half*)Cv + (size_t)z * sC_;
                    *(__half2*)(C + (size_t)row0 * ldc + col) =
                        __floats2half2_rn(acc[mt][nt][0], acc[mt][nt][1]);
                    *(__half2*)(C + (size_t)(row0 + 8) * ldc + col) =
                        __floats2half2_rn(acc[mt][nt][2], acc[mt][nt][3]);
                } else {
                    float* C = (float*)Cv + (size_t)z * sC_;
                    float2 v0, v1;
                    if (OUT == 1) {
                        v0 = make_float2(f2tf_f(acc[mt][nt][0]), f2tf_f(acc[mt][nt][1]));
                        v1 = make_float2(f2tf_f(acc[mt][nt][2]), f2tf_f(acc[mt][nt][3]));
                    } else {
                        v0 = make_float2(acc[mt][nt][0], acc[mt][nt][1]);
                        v1 = make_float2(acc[mt][nt][2], acc[mt][nt][3]);
                    }
                    *(float2*)(C + (size_t)row0 * ldc + col) = v0;
                    *(float2*)(C + (size_t)(row0 + 8) * ldc + col) = v1;
                }
            }
        }
    }
}

// ---------------- transpose wkv_b nope half -> fp16: out[h][c][d] ----------------
__global__ __launch_bounds__(256) void transpose_wkvb_kernel(
    const float* __restrict__ w, __half* __restrict__ out)
{
    __shared__ float tile[32][33];
    int h = blockIdx.z;
    int c0 = blockIdx.x * 32;
    int d0 = blockIdx.y * 32;
    int tx = threadIdx.x & 31, ty = threadIdx.x >> 5;
#pragma unroll
    for (int i = ty; i < 32; i += 8)
        tile[i][tx] = w[((size_t)h * 256 + d0 + i) * KVLORA + c0 + tx];
    __syncthreads();
#pragma unroll
    for (int i = ty; i < 32; i += 8)
        out[((size_t)h * KVLORA + c0 + i) * NOPEc + d0 + tx] = __float2half_rn(tile[tx][i]);
}

// ---------------- RMSNorm: fp32 in -> fp16 out ----------------
__global__ __launch_bounds__(256) void rmsnorm_h_kernel(
    const float* __restrict__ x, const float* __restrict__ w,
    __half* __restrict__ out, int L)
{
    __shared__ float sbuf[8];
    int row = blockIdx.x;
    const float* xr = x + (size_t)row * L;
    __half* orow = out + (size_t)row * L;
    float ss = 0.f;
    for (int i = threadIdx.x; i < L; i += 256) { float v = xr[i]; ss += v * v; }
#pragma unroll
    for (int o = 16; o; o >>= 1) ss += __shfl_xor_sync(0xffffffffu, ss, o);
    int warp = threadIdx.x >> 5, lane = threadIdx.x & 31;
    if (lane == 0) sbuf[warp] = ss;
    __syncthreads();
    if (threadIdx.x == 0) {
        float t = 0.f;
#pragma unroll
        for (int i = 0; i < 8; i++) t += sbuf[i];
        sbuf[0] = rsqrtf(t / (float)L + EPSc);
    }
    __syncthreads();
    float sc = sbuf[0];
    for (int i = threadIdx.x; i < L; i += 256) orow[i] = __float2half_rn(xr[i] * sc * w[i]);
}

// ---------------- kv split: rmsnorm(latent) + rope(k_pe) -> kfull (tf32) ----------------
__global__ __launch_bounds__(256) void kvprep_kernel(
    const float* __restrict__ kv, const float* __restrict__ w,
    const float* __restrict__ fcos, const float* __restrict__ fsin,
    float* __restrict__ kfull)
{
    __shared__ float sbuf[8];
    int row = blockIdx.x;
    int s = row & (Ss - 1);
    const float* kr = kv + (size_t)row * DF;
    float* kf = kfull + (size_t)row * DF;

    float ss = 0.f;
    for (int i = threadIdx.x; i < KVLORA; i += 256) { float v = kr[i]; ss += v * v; }
#pragma unroll
    for (int o = 16; o; o >>= 1) ss += __shfl_xor_sync(0xffffffffu, ss, o);
    int warp = threadIdx.x >> 5, lane = threadIdx.x & 31;
    if (lane == 0) sbuf[warp] = ss;
    __syncthreads();
    if (threadIdx.x == 0) {
        float t = 0.f;
#pragma unroll
        for (int i = 0; i < 8; i++) t += sbuf[i];
        sbuf[0] = rsqrtf(t / (float)KVLORA + EPSc);
    }
    __syncthreads();
    float sc = sbuf[0];
    for (int i = threadIdx.x; i < KVLORA; i += 256) kf[i] = f2tf_f(kr[i] * sc * w[i]);

    if (threadIdx.x < 32) {
        int i = threadIdx.x;
        float x0 = kr[KVLORA + 2 * i], x1 = kr[KVLORA + 2 * i + 1];
        float c = fcos[s * 32 + i], sn = fsin[s * 32 + i];
        kf[KVLORA + 2 * i]     = f2tf_f(x0 * c - x1 * sn);
        kf[KVLORA + 2 * i + 1] = f2tf_f(x0 * sn + x1 * c);
    }
}

// ---------------- rope(q_pe): fp16 q in -> qfull[:, :, 512:576] (tf32) ----------------
__global__ __launch_bounds__(512) void ropeq_kernel(
    const __half* __restrict__ q, const float* __restrict__ fcos,
    const float* __restrict__ fsin, float* __restrict__ qfull)
{
    int row = blockIdx.x;
    int s = row & (Ss - 1);
    int t = threadIdx.x;       // 512 = 16 heads * 32 pairs
    int h = t >> 5, i = t & 31;
    const __half* qr = q + (size_t)row * (Hh * QKH) + h * QKH + NOPEc;
    float x0 = __half2float(qr[2 * i]), x1 = __half2float(qr[2 * i + 1]);
    float c = fcos[s * 32 + i], sn = fsin[s * 32 + i];
    float* dst = qfull + ((size_t)row * Hh + h) * DF + KVLORA;
    dst[2 * i]     = f2tf_f(x0 * c - x1 * sn);
    dst[2 * i + 1] = f2tf_f(x0 * sn + x1 * c);
}

// ---------------- flash attention (tf32 mma, 32q x 32k tiles, 4-way k-split) ----------------
// qfull/kfull pre-rounded tf32 float; ctx output fp16 (feeds out-proj fp16 GEMM).
#define KSTR 588
#define PSTR 36
#define ATTN_SMEM_BYTES ((2 * 32 * KSTR + 4 * 32 * PSTR + 64) * 4)

__global__ __launch_bounds__(256, 1) void attn_kernel(
    const float* __restrict__ qfull, const float* __restrict__ kfull,
    __half* __restrict__ ctx)
{
    extern __shared__ float sm[];
    float* Qs   = sm;                   // 32 x 588
    float* Ks   = sm + 32 * KSTR;       // 32 x 588 (cols 0..511 double as V)
    float* Ps   = Ks + 32 * KSTR;       // 4 x (32 x 36)
    float* arow = Ps + 4 * 32 * PSTR;   // 32
    float* lrow = arow + 32;            // 32

    const int tid  = threadIdx.x;
    const int lane = tid & 31, warp = tid >> 5;
    const int g = lane >> 2, t = lane & 3;
    const int wk = warp & 3, wm = warp >> 2;
    const int bh = blockIdx.y;
    const int b = bh >> 4, h = bh & 15;
    const int s0 = blockIdx.x * 32;

    const int trow = tid >> 3, t8 = tid & 7;
    const uint32_t qdst = smem_u32(Qs) + ((uint32_t)trow * KSTR + (uint32_t)t8 * 4) * 4;
    const uint32_t kdst = smem_u32(Ks) + ((uint32_t)trow * KSTR + (uint32_t)t8 * 4) * 4;

    {
        const float4* src = (const float4*)(qfull + ((size_t)(b * Ss + s0 + trow) * Hh + h) * DF) + t8;
#pragma unroll
        for (int c = 0; c < 18; c++) cpa16(qdst + c * 128, src + c * 8);
        asm volatile("cp.async.commit_group;" ::: "memory");
    }

    float oacc[2][8][4];
#pragma unroll
    for (int mt = 0; mt < 2; mt++)
#pragma unroll
        for (int nt = 0; nt < 8; nt++)
#pragma unroll
            for (int e = 0; e < 4; e++) oacc[mt][nt][e] = 0.f;

    float mreg[4], lreg[4];
#pragma unroll
    for (int ii = 0; ii < 4; ii++) { mreg[ii] = -INFINITY; lreg[ii] = 0.f; }

    const int ntiles = s0 / 32 + 1;
    for (int kt = 0; kt < ntiles; kt++) {
        int t0 = kt * 32;
        {
            const float4* src = (const float4*)(kfull + (size_t)(b * Ss + t0 + trow) * DF) + t8;
#pragma unroll
            for (int c = 0; c < 18; c++) cpa16(kdst + c * 128, src + c * 8);
            asm volatile("cp.async.commit_group;" ::: "memory");
            asm volatile("cp.async.wait_group 0;" ::: "memory");
        }
        __syncthreads();

        // ---- scores ----
        {
            float sacc[4][4];
#pragma unroll
            for (int nt = 0; nt < 4; nt++)
#pragma unroll
                for (int e = 0; e < 4; e++) sacc[nt][e] = 0.f;

            const float* qb0 = Qs + (wm * 16 + g) * KSTR + wk * 144 + t;
#pragma unroll 3
            for (int ks = 0; ks < 18; ks++) {
                const float* qb = qb0 + ks * 8;
                uint32_t a[4];
                a[0] = __float_as_uint(qb[0]);
                a[1] = __float_as_uint(qb[8 * KSTR]);
                a[2] = __float_as_uint(qb[4]);
                a[3] = __float_as_uint(qb[8 * KSTR + 4]);
#pragma unroll
                for (int nt = 0; nt < 4; nt++) {
                    const float* kb = Ks + (nt * 8 + g) * KSTR + wk * 144 + ks * 8 + t;
                    uint32_t bf[2];
                    bf[0] = __float_as_uint(kb[0]);
                    bf[1] = __float_as_uint(kb[4]);
                    mma_tf32(sacc[nt], a, bf);
                }
            }
            float* Pw = Ps + wk * 32 * PSTR;
#pragma unroll
            for (int nt = 0; nt < 4; nt++) {
                int colb = nt * 8 + 2 * t;
                *(float2*)&Pw[(wm * 16 + g) * PSTR + colb] =
                    make_float2(sacc[nt][0], sacc[nt][1]);
                *(float2*)&Pw[(wm * 16 + g + 8) * PSTR + colb] =
                    make_float2(sacc[nt][2], sacc[nt][3]);
            }
        }
        __syncthreads();

        // ---- softmax ----
        {
#pragma unroll
            for (int ii = 0; ii < 4; ii++) {
                int i = warp * 4 + ii;
                float v = (Ps[i * PSTR + lane] +
                           Ps[32 * PSTR + i * PSTR + lane] +
                           Ps[64 * PSTR + i * PSTR + lane] +
                           Ps[96 * PSTR + i * PSTR + lane]) * SCALEc;
                if (t0 + lane > s0 + i) v = -INFINITY;
                float mx = v;
#pragma unroll
                for (int o = 16; o; o >>= 1) mx = fmaxf(mx, __shfl_xor_sync(0xffffffffu, mx, o));
                float mnew = fmaxf(mreg[ii], mx);
                float p = __expf(v - mnew);
                float psum = p;
#pragma unroll
                for (int o = 16; o; o >>= 1) psum += __shfl_xor_sync(0xffffffffu, psum, o);
                float al = __expf(mreg[ii] - mnew);
                lreg[ii] = lreg[ii] * al + psum;
                mreg[ii] = mnew;
                Ps[i * PSTR + lane] = f2tf_f(p);
                if (lane == 0) arow[i] = al;
            }
        }
        __syncthreads();

        // ---- PV ----
        {
#pragma unroll
            for (int mt = 0; mt < 2; mt++) {
                float al0 = arow[mt * 16 + g];
                float al1 = arow[mt * 16 + g + 8];
#pragma unroll
                for (int nt = 0; nt < 8; nt++) {
                    oacc[mt][nt][0] *= al0; oacc[mt][nt][1] *= al0;
                    oacc[mt][nt][2] *= al1; oacc[mt][nt][3] *= al1;
                }
            }
#pragma unroll
            for (int jb = 0; jb < 4; jb++) {
                int j0 = jb * 8;
                uint32_t pa[2][4];
#pragma unroll
                for (int mt = 0; mt < 2; mt++) {
                    const float* pb = Ps + (mt * 16 + g) * PSTR + j0 + t;
                    pa[mt][0] = __float_as_uint(pb[0]);
                    pa[mt][1] = __float_as_uint(pb[8 * PSTR]);
                    pa[mt][2] = __float_as_uint(pb[4]);
                    pa[mt][3] = __float_as_uint(pb[8 * PSTR + 4]);
                }
#pragma unroll
                for (int nt = 0; nt < 8; nt++) {
                    const float* vbp = Ks + (j0 + t) * KSTR + warp * 64 + nt * 8 + g;
                    uint32_t vb[2];
                    vb[0] = __float_as_uint(vbp[0]);
                    vb[1] = __float_as_uint(vbp[4 * KSTR]);
                    mma_tf32(oacc[0][nt], pa[0], vb);
                    mma_tf32(oacc[1][nt], pa[1], vb);
                }
            }
        }
        __syncthreads();
    }

    // ---- publish l, normalize, store ctx (fp16) ----
    if (lane == 0) {
#pragma unroll
        for (int ii = 0; ii < 4; ii++) lrow[warp * 4 + ii] = lreg[ii];
    }
    __syncthreads();
#pragma unroll
    for (int mt = 0; mt < 2; mt++) {
        int r0 = mt * 16 + g;
        int r1 = mt * 16 + g + 8;
        float inv0 = 1.0f / lrow[r0];
        float inv1 = 1.0f / lrow[r1];
        __half* cp0 = ctx + ((size_t)(b * Ss + s0 + r0) * Hh + h) * KVLORA + warp * 64;
        __half* cp1 = ctx + ((size_t)(b * Ss + s0 + r1) * Hh + h) * KVLORA + warp * 64;
#pragma unroll
        for (int nt = 0; nt < 8; nt++) {
            int col = nt * 8 + 2 * t;
            *(__half2*)(cp0 + col) =
                __floats2half2_rn(oacc[mt][nt][0] * inv0, oacc[mt][nt][1] * inv0);
            *(__half2*)(cp1 + col) =
                __floats2half2_rn(oacc[mt][nt][2] * inv1, oacc[mt][nt][3] * inv1);
        }
    }
}

// ---------------- launch ----------------
extern "C" void kernel_launch(void* const* d_in, const int* in_sizes, int n_in,
                              void* d_out, int out_size)
{
    const float* x     = (const float*)d_in[0];
    const float* fcos  = (const float*)d_in[1];
    const float* fsin  = (const float*)d_in[2];
    // d_in[3] = mask (causal; handled analytically)
    const float* wq_a  = (const float*)d_in[4];
    const float* q_ln  = (const float*)d_in[5];
    const float* wq_b  = (const float*)d_in[6];
    const float* wkv_a = (const float*)d_in[7];
    const float* kv_ln = (const float*)d_in[8];
    const float* wkv_b = (const float*)d_in[9];
    const float* wo    = (const float*)d_in[10];
    float* out = (float*)d_out;

    __half *xh, *wqa_h, *wqb_h, *wkva_h, *wo_h, *qlat_h, *q, *ctx, *attnout, *wkvbT, *wkvbV;
    float *qlat, *kv, *kfull, *qfull;
    cudaGetSymbolAddress((void**)&xh,      g_xh);
    cudaGetSymbolAddress((void**)&wqa_h,   g_wqa_h);
    cudaGetSymbolAddress((void**)&wqb_h,   g_wqb_h);
    cudaGetSymbolAddress((void**)&wkva_h,  g_wkva_h);
    cudaGetSymbolAddress((void**)&wo_h,    g_wo_h);
    cudaGetSymbolAddress((void**)&qlat,    g_qlat);
    cudaGetSymbolAddress((void**)&qlat_h,  g_qlat_h);
    cudaGetSymbolAddress((void**)&q,       g_q);
    cudaGetSymbolAddress((void**)&kv,      g_kv);
    cudaGetSymbolAddress((void**)&kfull,   g_kfull);
    cudaGetSymbolAddress((void**)&qfull,   g_qfull);
    cudaGetSymbolAddress((void**)&ctx,     g_ctx);
    cudaGetSymbolAddress((void**)&attnout, g_attnout);
    cudaGetSymbolAddress((void**)&wkvbT,   g_wkvbT);
    cudaGetSymbolAddress((void**)&wkvbV,   g_wkvbV);

    cudaFuncSetAttribute(gemm_f16_kernel<0>, cudaFuncAttributeMaxDynamicSharedMemorySize, GSMEM);
    cudaFuncSetAttribute(gemm_f16_kernel<1>, cudaFuncAttributeMaxDynamicSharedMemorySize, GSMEM);
    cudaFuncSetAttribute(gemm_f16_kernel<2>, cudaFuncAttributeMaxDynamicSharedMemorySize, GSMEM);
    cudaFuncSetAttribute(attn_kernel, cudaFuncAttributeMaxDynamicSharedMemorySize,
                         ATTN_SMEM_BYTES);

    dim3 blk(256);

    // 0a. fp32 -> fp16 conversions
    auto tohalf = [&](const float* s, __half* d, size_t n) {
        int n8 = (int)(n / 8);
        tohalf_kernel<<<(n8 + 255) / 256, blk>>>((const float4*)s, (uint4*)d, n8);
    };
    tohalf(x,     xh,     (size_t)ROWS * DIMc);
    tohalf(wq_a,  wqa_h,  (size_t)QLORA * DIMc);
    tohalf(wq_b,  wqb_h,  (size_t)(Hh * QKH) * QLORA);
    tohalf(wkv_a, wkva_h, (size_t)DF * DIMc);
    tohalf(wo,    wo_h,   (size_t)DIMc * DIMc);
    wkvbv_kernel<<<(Hh * VDIMc * KVLORA / 8 + 255) / 256, blk>>>(wkv_b, wkvbV);
    transpose_wkvb_kernel<<<dim3(KVLORA / 32, NOPEc / 32, Hh), blk>>>(wkv_b, wkvbT);

    // 1. q_lat_pre = xh @ wqa_h^T      (4096 x 1536, K=2048) -> fp32
    gemm_f16_kernel<0><<<dim3(QLORA / 128, ROWS / 128, 1), blk, GSMEM>>>(
        xh, DIMc, 0, wqa_h, DIMc, 0, qlat, QLORA, 0, ROWS, QLORA, DIMc);

    // 2. rmsnorm -> fp16
    rmsnorm_h_kernel<<<ROWS, 256>>>(qlat, q_ln, qlat_h, QLORA);

    // 3. q = qlat_h @ wqb_h^T          (4096 x 3072, K=1536) -> fp16
    gemm_f16_kernel<2><<<dim3((Hh * QKH) / 128, ROWS / 128, 1), blk, GSMEM>>>(
        qlat_h, QLORA, 0, wqb_h, QLORA, 0, q, Hh * QKH, 0, ROWS, Hh * QKH, QLORA);

    // 4. kv = xh @ wkva_h^T            (4096 x 576, K=2048) -> fp32
    gemm_f16_kernel<0><<<dim3((DF + 127) / 128, ROWS / 128, 1), blk, GSMEM>>>(
        xh, DIMc, 0, wkva_h, DIMc, 0, kv, DF, 0, ROWS, DF, DIMc);

    // 5. kfull = [rmsnorm(kv_lat), rope(k_pe)]  (tf32 float)
    kvprep_kernel<<<ROWS, 256>>>(kv, kv_ln, fcos, fsin, kfull);

    // 6. q-absorb per head -> qfull[:, h, :512]  (tf32-rounded float)
    gemm_f16_kernel<1><<<dim3(KVLORA / 128, ROWS / 128, Hh), blk, GSMEM>>>(
        q, Hh * QKH, QKH,
        wkvbT, NOPEc, (long)KVLORA * NOPEc,
        qfull, Hh * DF, DF,
        ROWS, KVLORA, NOPEc);

    // 7. qfull[:, h, 512:576] = rope(q_pe)  (tf32 float)
    ropeq_kernel<<<ROWS, 512>>>(q, fcos, fsin, qfull);

    // 8. flash attention -> ctx (fp16)
    attn_kernel<<<dim3(Ss / 32, Bb * Hh), 256, ATTN_SMEM_BYTES>>>(qfull, kfull, ctx);

    // 9. per-head out-proj: attnout = ctx_h @ wkvbV[h]^T -> fp16
    gemm_f16_kernel<2><<<dim3(1, ROWS / 128, Hh), blk, GSMEM>>>(
        ctx, Hh * KVLORA, KVLORA,
        wkvbV, KVLORA, (long)VDIMc * KVLORA,
        attnout, DIMc, VDIMc,
        ROWS, VDIMc, KVLORA);

    // 10. out = attnout @ wo_h^T       (4096 x 2048, K=2048) -> fp32
    gemm_f16_kernel<0><<<dim3(DIMc / 128, ROWS / 128, 1), blk, GSMEM>>>(
        attnout, DIMc, 0, wo_h, DIMc, 0, out, DIMc, 0, ROWS, DIMc, DIMc);
}

// round 15
// speedup vs baseline: 2.1991x; 1.6797x over previous
#include <cuda_runtime.h>
#include <cuda_fp16.h>
#include <math.h>
#include <stdint.h>

// ---------------- problem constants ----------------
#define Bb     2
#define Ss     2048
#define DIMc   2048
#define Hh     16
#define QLORA  1536
#define KVLORA 512
#define NOPEc  128
#define ROPEc  64
#define VDIMc  128
#define QKH    192            // NOPE + ROPE
#define ROWS   (Bb*Ss)        // 4096
#define DF     576            // 512 latent + 64 rope
#define SCALEc 0.07216878364870322f  // 1/sqrt(192)
#define EPSc   1e-6f

// ---------------- scratch (static device arrays; no allocation) ----------------
__device__ __half g_xh[(size_t)ROWS * DIMc];             // fp16 copy of x
__device__ __half g_wqa_h[(size_t)QLORA * DIMc];
__device__ __half g_wqb_h[(size_t)(Hh * QKH) * QLORA];
__device__ __half g_wkva_h[(size_t)DF * DIMc];
__device__ __half g_wo_h[(size_t)DIMc * DIMc];
__device__ float  g_qlat[(size_t)ROWS * QLORA];          // fp32 (pre-rmsnorm)
__device__ __half g_qlat_h[(size_t)ROWS * QLORA];        // fp16 (post-rmsnorm)
__device__ __half g_q[(size_t)ROWS * (Hh * QKH)];        // fp16
__device__ float  g_kv[(size_t)ROWS * DF];               // fp32
__device__ __half g_kfull[(size_t)ROWS * DF];            // fp16 (attention operand)
__device__ __half g_qfull[(size_t)ROWS * Hh * DF];       // fp16 (attention operand)
__device__ __half g_ctx[(size_t)ROWS * Hh * KVLORA];     // fp16
__device__ __half g_attnout[(size_t)ROWS * DIMc];        // fp16
__device__ __half g_wkvbT[(size_t)Hh * KVLORA * NOPEc];  // fp16 transposed nope half
__device__ __half g_wkvbV[(size_t)Hh * VDIMc * KVLORA];  // fp16 v half

// ================= helpers =================
__device__ __forceinline__ void mma_f16(float* d, const uint32_t* a, const uint32_t* b) {
    asm volatile(
        "mma.sync.aligned.m16n8k16.row.col.f32.f16.f16.f32 "
        "{%0,%1,%2,%3}, {%4,%5,%6,%7}, {%8,%9}, {%0,%1,%2,%3};"
        : "+f"(d[0]), "+f"(d[1]), "+f"(d[2]), "+f"(d[3])
        : "r"(a[0]), "r"(a[1]), "r"(a[2]), "r"(a[3]), "r"(b[0]), "r"(b[1]));
}
__device__ __forceinline__ uint32_t smem_u32(const void* p) {
    uint32_t a;
    asm("{ .reg .u64 t; cvta.to.shared.u64 t, %1; cvt.u32.u64 %0, t; }" : "=r"(a) : "l"(p));
    return a;
}
__device__ __forceinline__ void cpa16(uint32_t dst, const void* src) {
    asm volatile("cp.async.cg.shared.global [%0], [%1], 16;" :: "r"(dst), "l"(src));
}
__device__ __forceinline__ void cpa16z(uint32_t dst, const void* src, uint32_t sz) {
    asm volatile("cp.async.cg.shared.global [%0], [%1], 16, %2;" :: "r"(dst), "l"(src), "r"(sz));
}
__device__ __forceinline__ void ldsm_x2_trans(uint32_t& r0, uint32_t& r1, uint32_t addr) {
    asm volatile("ldmatrix.sync.aligned.m8n8.x2.trans.shared.b16 {%0,%1}, [%2];"
                 : "=r"(r0), "=r"(r1) : "r"(addr));
}

// ---------------- bulk fp32 -> fp16 convert (8 elements/thread) ----------------
__global__ __launch_bounds__(256) void tohalf_kernel(
    const float4* __restrict__ src, uint4* __restrict__ dst, int n8)
{
    int i = blockIdx.x * 256 + threadIdx.x;
    if (i < n8) {
        float4 a = src[2 * i], b = src[2 * i + 1];
        __half2 h0 = __floats2half2_rn(a.x, a.y);
        __half2 h1 = __floats2half2_rn(a.z, a.w);
        __half2 h2 = __floats2half2_rn(b.x, b.y);
        __half2 h3 = __floats2half2_rn(b.z, b.w);
        uint4 o;
        o.x = *(uint32_t*)&h0; o.y = *(uint32_t*)&h1;
        o.z = *(uint32_t*)&h2; o.w = *(uint32_t*)&h3;
        dst[i] = o;
    }
}

// ---------------- wkv_b v-half -> fp16 contiguous copy [h][128][512] ----------------
__global__ __launch_bounds__(256) void wkvbv_kernel(
    const float* __restrict__ w, __half* __restrict__ out)
{
    int i = blockIdx.x * 256 + threadIdx.x;
    int n8 = Hh * VDIMc * KVLORA / 8;
    if (i < n8) {
        int per_h = VDIMc * KVLORA / 8;
        int h = i / per_h;
        int rem = i - h * per_h;
        const float4* src = (const float4*)(w + ((size_t)h * (NOPEc + VDIMc) + NOPEc) * KVLORA);
        float4 a = src[2 * rem], b = src[2 * rem + 1];
        __half2 h0 = __floats2half2_rn(a.x, a.y);
        __half2 h1 = __floats2half2_rn(a.z, a.w);
        __half2 h2 = __floats2half2_rn(b.x, b.y);
        __half2 h3 = __floats2half2_rn(b.z, b.w);
        uint4 o;
        o.x = *(uint32_t*)&h0; o.y = *(uint32_t*)&h1;
        o.z = *(uint32_t*)&h2; o.w = *(uint32_t*)&h3;
        ((uint4*)(out + (size_t)h * VDIMc * KVLORA))[rem] = o;
    }
}

// ================= fp16 tensor-core GEMM (TB: C = A @ B^T) =================
// OUT: 0 = fp32 raw, 2 = fp16. (R13-verified.)
#define GSMEM (16384 * 4)

template<int OUT>
__global__ __launch_bounds__(256) void gemm_f16_kernel(
    const __half* __restrict__ A, int lda, long sA_,
    const __half* __restrict__ B, int ldb, long sB_,
    void* __restrict__ Cv, int ldc, long sC_,
    int M, int N, int K)
{
    extern __shared__ __align__(16) uint32_t dsm[];

    int z = blockIdx.z;
    A += (size_t)z * sA_;
    B += (size_t)z * sB_;

    const int tid    = threadIdx.x;
    const int lane   = tid & 31;
    const int warp   = tid >> 5;
    const int warp_m = warp >> 2;
    const int warp_n = warp & 3;
    const int g = lane >> 2, t = lane & 3;
    const int m0 = blockIdx.y * 128;
    const int n0 = blockIdx.x * 128;
    const int KT = K >> 5;

    float acc[4][4][4];
#pragma unroll
    for (int mt = 0; mt < 4; mt++)
#pragma unroll
        for (int nt = 0; nt < 4; nt++)
#pragma unroll
            for (int e = 0; e < 4; e++) acc[mt][nt][e] = 0.f;

    const int lr0 = tid >> 2;
    const int lkw = (tid & 3) << 2;
    const uint32_t smem_base = smem_u32(dsm);

    auto load_stage = [&](int chunk, int s) {
        int k0 = chunk << 5;
        uint32_t abase = smem_base + (uint32_t)s * 8192;
        uint32_t bbase = abase + 32768;
#pragma unroll
        for (int i = 0; i < 2; i++) {
            int r = lr0 + i * 64;
            uint32_t off = (uint32_t)(r * 16 + (lkw ^ (((r >> 1) & 3) << 2))) * 4;
            cpa16(abase + off, A + (size_t)(m0 + r) * lda + k0 + lkw * 2);
            cpa16z(bbase + off, B + (size_t)(n0 + r) * ldb + k0 + lkw * 2,
                   (n0 + r < N) ? 16u : 0u);
        }
    };

    const int fr = (g >> 1) << 2;

    auto compute = [&](int s) {
        const uint32_t* As = dsm + (uint32_t)s * 2048;
        const uint32_t* Bs = As + 8192;
#pragma unroll
        for (int ks = 0; ks < 2; ks++) {
            const int xk  = ((ks << 3) | t) ^ fr;
            const int xk2 = xk ^ 4;
            uint32_t af[4][4];
            uint32_t bf[4][2];
#pragma unroll
            for (int mt = 0; mt < 4; mt++) {
                int base = (warp_m * 64 + mt * 16 + g) * 16;
                af[mt][0] = As[base + xk];
                af[mt][1] = As[base + 128 + xk];
                af[mt][2] = As[base + xk2];
                af[mt][3] = As[base + 128 + xk2];
            }
#pragma unroll
            for (int nt = 0; nt < 4; nt++) {
                int base = (warp_n * 32 + nt * 8 + g) * 16;
                bf[nt][0] = Bs[base + xk];
                bf[nt][1] = Bs[base + xk2];
            }
#pragma unroll
            for (int mt = 0; mt < 4; mt++)
#pragma unroll
                for (int nt = 0; nt < 4; nt++)
                    mma_f16(acc[mt][nt], af[mt], bf[nt]);
        }
    };

    const int PRE = (KT < 3) ? KT : 3;
    for (int s = 0; s < PRE; s++) {
        load_stage(s, s);
        asm volatile("cp.async.commit_group;" ::: "memory");
    }

    for (int kt = 0; kt < KT; kt++) {
        asm volatile("cp.async.wait_group 2;" ::: "memory");
        __syncthreads();
        if (kt + 3 < KT) load_stage(kt + 3, (kt + 3) & 3);
        asm volatile("cp.async.commit_group;" ::: "memory");
        compute(kt & 3);
    }

#pragma unroll
    for (int mt = 0; mt < 4; mt++) {
        int row0 = m0 + warp_m * 64 + mt * 16 + g;
#pragma unroll
        for (int nt = 0; nt < 4; nt++) {
            int col = n0 + warp_n * 32 + nt * 8 + 2 * t;
            if (col < N) {
                if (OUT == 2) {
                    __half* C = (__half*)Cv + (size_t)z * sC_;
                    *(__half2*)(C + (size_t)row0 * ldc + col) =
                        __floats2half2_rn(acc[mt][nt][0], acc[mt][nt][1]);
                    *(__half2*)(C + (size_t)(row0 + 8) * ldc + col) =
                        __floats2half2_rn(acc[mt][nt][2], acc[mt][nt][3]);
                } else {
                    float* C = (float*)Cv + (size_t)z * sC_;
                    *(float2*)(C + (size_t)row0 * ldc + col) =
                        make_float2(acc[mt][nt][0], acc[mt][nt][1]);
                    *(float2*)(C + (size_t)(row0 + 8) * ldc + col) =
                        make_float2(acc[mt][nt][2], acc[mt][nt][3]);
                }
            }
        }
    }
}

// ---------------- transpose wkv_b nope half -> fp16: out[h][c][d] ----------------
__global__ __launch_bounds__(256) void transpose_wkvb_kernel(
    const float* __restrict__ w, __half* __restrict__ out)
{
    __shared__ float tile[32][33];
    int h = blockIdx.z;
    int c0 = blockIdx.x * 32;
    int d0 = blockIdx.y * 32;
    int tx = threadIdx.x & 31, ty = threadIdx.x >> 5;
#pragma unroll
    for (int i = ty; i < 32; i += 8)
        tile[i][tx] = w[((size_t)h * 256 + d0 + i) * KVLORA + c0 + tx];
    __syncthreads();
#pragma unroll
    for (int i = ty; i < 32; i += 8)
        out[((size_t)h * KVLORA + c0 + i) * NOPEc + d0 + tx] = __float2half_rn(tile[tx][i]);
}

// ---------------- RMSNorm: fp32 in -> fp16 out ----------------
__global__ __launch_bounds__(256) void rmsnorm_h_kernel(
    const float* __restrict__ x, const float* __restrict__ w,
    __half* __restrict__ out, int L)
{
    __shared__ float sbuf[8];
    int row = blockIdx.x;
    const float* xr = x + (size_t)row * L;
    __half* orow = out + (size_t)row * L;
    float ss = 0.f;
    for (int i = threadIdx.x; i < L; i += 256) { float v = xr[i]; ss += v * v; }
#pragma unroll
    for (int o = 16; o; o >>= 1) ss += __shfl_xor_sync(0xffffffffu, ss, o);
    int warp = threadIdx.x >> 5, lane = threadIdx.x & 31;
    if (lane == 0) sbuf[warp] = ss;
    __syncthreads();
    if (threadIdx.x == 0) {
        float t = 0.f;
#pragma unroll
        for (int i = 0; i < 8; i++) t += sbuf[i];
        sbuf[0] = rsqrtf(t / (float)L + EPSc);
    }
    __syncthreads();
    float sc = sbuf[0];
    for (int i = threadIdx.x; i < L; i += 256) orow[i] = __float2half_rn(xr[i] * sc * w[i]);
}

// ---------------- kv split: rmsnorm(latent) + rope(k_pe) -> kfull (fp16) ----------------
__global__ __launch_bounds__(256) void kvprep_kernel(
    const float* __restrict__ kv, const float* __restrict__ w,
    const float* __restrict__ fcos, const float* __restrict__ fsin,
    __half* __restrict__ kfull)
{
    __shared__ float sbuf[8];
    int row = blockIdx.x;
    int s = row & (Ss - 1);
    const float* kr = kv + (size_t)row * DF;
    __half* kf = kfull + (size_t)row * DF;

    float ss = 0.f;
    for (int i = threadIdx.x; i < KVLORA; i += 256) { float v = kr[i]; ss += v * v; }
#pragma unroll
    for (int o = 16; o; o >>= 1) ss += __shfl_xor_sync(0xffffffffu, ss, o);
    int warp = threadIdx.x >> 5, lane = threadIdx.x & 31;
    if (lane == 0) sbuf[warp] = ss;
    __syncthreads();
    if (threadIdx.x == 0) {
        float t = 0.f;
#pragma unroll
        for (int i = 0; i < 8; i++) t += sbuf[i];
        sbuf[0] = rsqrtf(t / (float)KVLORA + EPSc);
    }
    __syncthreads();
    float sc = sbuf[0];
    for (int i = threadIdx.x; i < KVLORA; i += 256) kf[i] = __float2half_rn(kr[i] * sc * w[i]);

    if (threadIdx.x < 32) {
        int i = threadIdx.x;
        float x0 = kr[KVLORA + 2 * i], x1 = kr[KVLORA + 2 * i + 1];
        float c = fcos[s * 32 + i], sn = fsin[s * 32 + i];
        kf[KVLORA + 2 * i]     = __float2half_rn(x0 * c - x1 * sn);
        kf[KVLORA + 2 * i + 1] = __float2half_rn(x0 * sn + x1 * c);
    }
}

// ---------------- rope(q_pe): fp16 q in -> qfull[:, :, 512:576] (fp16) ----------------
__global__ __launch_bounds__(512) void ropeq_kernel(
    const __half* __restrict__ q, const float* __restrict__ fcos,
    const float* __restrict__ fsin, __half* __restrict__ qfull)
{
    int row = blockIdx.x;
    int s = row & (Ss - 1);
    int t = threadIdx.x;
    int h = t >> 5, i = t & 31;
    const __half* qr = q + (size_t)row * (Hh * QKH) + h * QKH + NOPEc;
    float x0 = __half2float(qr[2 * i]), x1 = __half2float(qr[2 * i + 1]);
    float c = fcos[s * 32 + i], sn = fsin[s * 32 + i];
    __half* dst = qfull + ((size_t)row * Hh + h) * DF + KVLORA;
    dst[2 * i]     = __float2half_rn(x0 * c - x1 * sn);
    dst[2 * i + 1] = __float2half_rn(x0 * sn + x1 * c);
}

// ---------------- flash attention (fp16 mma m16n8k16, 32q x 32k tiles) ----------------
// Q/K tiles fp16, stride 584 halfs (292 words === 4 mod 32: conflict-free frag
// loads AND conflict-free ldmatrix row addressing). Scores: 2(m) x 4(k-split)
// warps, fp32 partials summed in softmax. PV: B operand via ldmatrix.x2.trans.
// P fp16 at stride 72 halfs (36 words === 4 mod 32).
#define HSTR 584
#define PSTRF 36
#define PHSTR 72
#define QS_OFF   0
#define KS_OFF   (32 * HSTR * 2)                 // 37376
#define PS_OFF   (2 * 32 * HSTR * 2)             // 74752
#define PH_OFF   (PS_OFF + 4 * 32 * PSTRF * 4)   // 93184
#define AROW_OFF (PH_OFF + 32 * PHSTR * 2)       // 97792
#define ATTN_SMEM_BYTES (AROW_OFF + 64 * 4)      // 98048

__global__ __launch_bounds__(256, 2) void attn_kernel(
    const __half* __restrict__ qfull, const __half* __restrict__ kfull,
    __half* __restrict__ ctx)
{
    extern __shared__ char smraw[];
    __half* Qs   = (__half*)(smraw + QS_OFF);
    __half* Ks   = (__half*)(smraw + KS_OFF);
    float*  Ps   = (float*)(smraw + PS_OFF);
    __half* Ph   = (__half*)(smraw + PH_OFF);
    float*  arow = (float*)(smraw + AROW_OFF);
    float*  lrow = arow + 32;

    const int tid  = threadIdx.x;
    const int lane = tid & 31, warp = tid >> 5;
    const int g = lane >> 2, t = lane & 3;
    const int wk = warp & 3, wm = warp >> 2;   // scores: 2(m) x 4(k-split)
    const int bh = blockIdx.y;
    const int b = bh >> 4, h = bh & 15;
    const int s0 = blockIdx.x * 32;

    const int trow = tid >> 3, t8 = tid & 7;   // copy: 8 thr/row, 9 x 16B chunks
    const uint32_t qdst = smem_u32(Qs) + (uint32_t)trow * (HSTR * 2) + (uint32_t)t8 * 16;
    const uint32_t kdst = smem_u32(Ks) + (uint32_t)trow * (HSTR * 2) + (uint32_t)t8 * 16;

    // ---- load Q tile ----
    {
        const char* src = (const char*)(qfull + ((size_t)(b * Ss + s0 + trow) * Hh + h) * DF) + t8 * 16;
#pragma unroll
        for (int c = 0; c < 9; c++) cpa16(qdst + c * 128, src + c * 128);
        asm volatile("cp.async.commit_group;" ::: "memory");
    }

    float oacc[2][8][4];
#pragma unroll
    for (int mt = 0; mt < 2; mt++)
#pragma unroll
        for (int nt = 0; nt < 8; nt++)
#pragma unroll
            for (int e = 0; e < 4; e++) oacc[mt][nt][e] = 0.f;

    float mreg[4], lreg[4];
#pragma unroll
    for (int ii = 0; ii < 4; ii++) { mreg[ii] = -INFINITY; lreg[ii] = 0.f; }

    const int ntiles = s0 / 32 + 1;
    for (int kt = 0; kt < ntiles; kt++) {
        int t0 = kt * 32;
        // ---- load K tile ----
        {
            const char* src = (const char*)(kfull + (size_t)(b * Ss + t0 + trow) * DF) + t8 * 16;
#pragma unroll
            for (int c = 0; c < 9; c++) cpa16(kdst + c * 128, src + c * 128);
            asm volatile("cp.async.commit_group;" ::: "memory");
            asm volatile("cp.async.wait_group 0;" ::: "memory");
        }
        __syncthreads();

        // ---- scores: warp (wm, wk) -> m16 x n32, k-quarter = 144 halfs (9 K16 steps) ----
        {
            float sacc[4][4];
#pragma unroll
            for (int nt = 0; nt < 4; nt++)
#pragma unroll
                for (int e = 0; e < 4; e++) sacc[nt][e] = 0.f;

            const __half* qb0 = Qs + (wm * 16 + g) * HSTR + wk * 144 + 2 * t;
#pragma unroll 3
            for (int ks = 0; ks < 9; ks++) {
                const __half* qb = qb0 + ks * 16;
                uint32_t a[4];
                a[0] = *(const uint32_t*)(qb);
                a[1] = *(const uint32_t*)(qb + 8 * HSTR);
                a[2] = *(const uint32_t*)(qb + 8);
                a[3] = *(const uint32_t*)(qb + 8 * HSTR + 8);
#pragma unroll
                for (int nt = 0; nt < 4; nt++) {
                    const __half* kb = Ks + (nt * 8 + g) * HSTR + wk * 144 + ks * 16 + 2 * t;
                    uint32_t bf[2];
                    bf[0] = *(const uint32_t*)(kb);
                    bf[1] = *(const uint32_t*)(kb + 8);
                    mma_f16(sacc[nt], a, bf);
                }
            }
            float* Pw = Ps + wk * 32 * PSTRF;
#pragma unroll
            for (int nt = 0; nt < 4; nt++) {
                int colb = nt * 8 + 2 * t;
                *(float2*)&Pw[(wm * 16 + g) * PSTRF + colb] =
                    make_float2(sacc[nt][0], sacc[nt][1]);
                *(float2*)&Pw[(wm * 16 + g + 8) * PSTRF + colb] =
                    make_float2(sacc[nt][2], sacc[nt][3]);
            }
        }
        __syncthreads();

        // ---- softmax: warp owns rows 4*warp..+3, lane = key j ----
        {
#pragma unroll
            for (int ii = 0; ii < 4; ii++) {
                int i = warp * 4 + ii;
                float v = (Ps[i * PSTRF + lane] +
                           Ps[32 * PSTRF + i * PSTRF + lane] +
                           Ps[64 * PSTRF + i * PSTRF + lane] +
                           Ps[96 * PSTRF + i * PSTRF + lane]) * SCALEc;
                if (t0 + lane > s0 + i) v = -INFINITY;
                float mx = v;
#pragma unroll
                for (int o = 16; o; o >>= 1) mx = fmaxf(mx, __shfl_xor_sync(0xffffffffu, mx, o));
                float mnew = fmaxf(mreg[ii], mx);
                float p = __expf(v - mnew);
                float psum = p;
#pragma unroll
                for (int o = 16; o; o >>= 1) psum += __shfl_xor_sync(0xffffffffu, psum, o);
                float al = __expf(mreg[ii] - mnew);
                lreg[ii] = lreg[ii] * al + psum;
                mreg[ii] = mnew;
                Ph[i * PHSTR + lane] = __float2half_rn(p);
                if (lane == 0) arow[i] = al;
            }
        }
        __syncthreads();

        // ---- PV: warp owns all 32 rows x cols [warp*64, warp*64+64) ----
        {
#pragma unroll
            for (int mt = 0; mt < 2; mt++) {
                float al0 = arow[mt * 16 + g];
                float al1 = arow[mt * 16 + g + 8];
#pragma unroll
                for (int nt = 0; nt < 8; nt++) {
                    oacc[mt][nt][0] *= al0; oacc[mt][nt][1] *= al0;
                    oacc[mt][nt][2] *= al1; oacc[mt][nt][3] *= al1;
                }
            }
#pragma unroll
            for (int jb = 0; jb < 2; jb++) {
                int j0 = jb * 16;
                uint32_t pa[2][4];
#pragma unroll
                for (int mt = 0; mt < 2; mt++) {
                    const __half* pb = Ph + (mt * 16 + g) * PHSTR + j0 + 2 * t;
                    pa[mt][0] = *(const uint32_t*)(pb);
                    pa[mt][1] = *(const uint32_t*)(pb + 8 * PHSTR);
                    pa[mt][2] = *(const uint32_t*)(pb + 8);
                    pa[mt][3] = *(const uint32_t*)(pb + 8 * PHSTR + 8);
                }
                // V rows j0 + (lane&15), 8-half chunks at col warp*64 + nt*8
                uint32_t vbase = smem_u32(Ks) +
                    (uint32_t)(j0 + (lane & 15)) * (HSTR * 2) + (uint32_t)(warp * 64) * 2;
#pragma unroll
                for (int nt = 0; nt < 8; nt++) {
                    uint32_t vb[2];
                    ldsm_x2_trans(vb[0], vb[1], vbase + nt * 16);
                    mma_f16(oacc[0][nt], pa[0], vb);
                    mma_f16(oacc[1][nt], pa[1], vb);
                }
            }
        }
        __syncthreads();
    }

    // ---- publish l, normalize, store ctx (fp16) ----
    if (lane == 0) {
#pragma unroll
        for (int ii = 0; ii < 4; ii++) lrow[warp * 4 + ii] = lreg[ii];
    }
    __syncthreads();
#pragma unroll
    for (int mt = 0; mt < 2; mt++) {
        int r0 = mt * 16 + g;
        int r1 = mt * 16 + g + 8;
        float inv0 = 1.0f / lrow[r0];
        float inv1 = 1.0f / lrow[r1];
        __half* cp0 = ctx + ((size_t)(b * Ss + s0 + r0) * Hh + h) * KVLORA + warp * 64;
        __half* cp1 = ctx + ((size_t)(b * Ss + s0 + r1) * Hh + h) * KVLORA + warp * 64;
#pragma unroll
        for (int nt = 0; nt < 8; nt++) {
            int col = nt * 8 + 2 * t;
            *(__half2*)(cp0 + col) =
                __floats2half2_rn(oacc[mt][nt][0] * inv0, oacc[mt][nt][1] * inv0);
            *(__half2*)(cp1 + col) =
                __floats2half2_rn(oacc[mt][nt][2] * inv1, oacc[mt][nt][3] * inv1);
        }
    }
}

// ---------------- launch ----------------
extern "C" void kernel_launch(void* const* d_in, const int* in_sizes, int n_in,
                              void* d_out, int out_size)
{
    const float* x     = (const float*)d_in[0];
    const float* fcos  = (const float*)d_in[1];
    const float* fsin  = (const float*)d_in[2];
    // d_in[3] = mask (causal; handled analytically)
    const float* wq_a  = (const float*)d_in[4];
    const float* q_ln  = (const float*)d_in[5];
    const float* wq_b  = (const float*)d_in[6];
    const float* wkv_a = (const float*)d_in[7];
    const float* kv_ln = (const float*)d_in[8];
    const float* wkv_b = (const float*)d_in[9];
    const float* wo    = (const float*)d_in[10];
    float* out = (float*)d_out;

    __half *xh, *wqa_h, *wqb_h, *wkva_h, *wo_h, *qlat_h, *q, *ctx, *attnout, *wkvbT, *wkvbV;
    __half *kfull, *qfull;
    float *qlat, *kv;
    cudaGetSymbolAddress((void**)&xh,      g_xh);
    cudaGetSymbolAddress((void**)&wqa_h,   g_wqa_h);
    cudaGetSymbolAddress((void**)&wqb_h,   g_wqb_h);
    cudaGetSymbolAddress((void**)&wkva_h,  g_wkva_h);
    cudaGetSymbolAddress((void**)&wo_h,    g_wo_h);
    cudaGetSymbolAddress((void**)&qlat,    g_qlat);
    cudaGetSymbolAddress((void**)&qlat_h,  g_qlat_h);
    cudaGetSymbolAddress((void**)&q,       g_q);
    cudaGetSymbolAddress((void**)&kv,      g_kv);
    cudaGetSymbolAddress((void**)&kfull,   g_kfull);
    cudaGetSymbolAddress((void**)&qfull,   g_qfull);
    cudaGetSymbolAddress((void**)&ctx,     g_ctx);
    cudaGetSymbolAddress((void**)&attnout, g_attnout);
    cudaGetSymbolAddress((void**)&wkvbT,   g_wkvbT);
    cudaGetSymbolAddress((void**)&wkvbV,   g_wkvbV);

    cudaFuncSetAttribute(gemm_f16_kernel<0>, cudaFuncAttributeMaxDynamicSharedMemorySize, GSMEM);
    cudaFuncSetAttribute(gemm_f16_kernel<2>, cudaFuncAttributeMaxDynamicSharedMemorySize, GSMEM);
    cudaFuncSetAttribute(attn_kernel, cudaFuncAttributeMaxDynamicSharedMemorySize,
                         ATTN_SMEM_BYTES);

    dim3 blk(256);

    // 0a. fp32 -> fp16 conversions
    auto tohalf = [&](const float* s, __half* d, size_t n) {
        int n8 = (int)(n / 8);
        tohalf_kernel<<<(n8 + 255) / 256, blk>>>((const float4*)s, (uint4*)d, n8);
    };
    tohalf(x,     xh,     (size_t)ROWS * DIMc);
    tohalf(wq_a,  wqa_h,  (size_t)QLORA * DIMc);
    tohalf(wq_b,  wqb_h,  (size_t)(Hh * QKH) * QLORA);
    tohalf(wkv_a, wkva_h, (size_t)DF * DIMc);
    tohalf(wo,    wo_h,   (size_t)DIMc * DIMc);
    wkvbv_kernel<<<(Hh * VDIMc * KVLORA / 8 + 255) / 256, blk>>>(wkv_b, wkvbV);
    transpose_wkvb_kernel<<<dim3(KVLORA / 32, NOPEc / 32, Hh), blk>>>(wkv_b, wkvbT);

    // 1. q_lat_pre = xh @ wqa_h^T      (4096 x 1536, K=2048) -> fp32
    gemm_f16_kernel<0><<<dim3(QLORA / 128, ROWS / 128, 1), blk, GSMEM>>>(
        xh, DIMc, 0, wqa_h, DIMc, 0, qlat, QLORA, 0, ROWS, QLORA, DIMc);

    // 2. rmsnorm -> fp16
    rmsnorm_h_kernel<<<ROWS, 256>>>(qlat, q_ln, qlat_h, QLORA);

    // 3. q = qlat_h @ wqb_h^T          (4096 x 3072, K=1536) -> fp16
    gemm_f16_kernel<2><<<dim3((Hh * QKH) / 128, ROWS / 128, 1), blk, GSMEM>>>(
        qlat_h, QLORA, 0, wqb_h, QLORA, 0, q, Hh * QKH, 0, ROWS, Hh * QKH, QLORA);

    // 4. kv = xh @ wkva_h^T            (4096 x 576, K=2048) -> fp32
    gemm_f16_kernel<0><<<dim3((DF + 127) / 128, ROWS / 128, 1), blk, GSMEM>>>(
        xh, DIMc, 0, wkva_h, DIMc, 0, kv, DF, 0, ROWS, DF, DIMc);

    // 5. kfull = [rmsnorm(kv_lat), rope(k_pe)]  (fp16)
    kvprep_kernel<<<ROWS, 256>>>(kv, kv_ln, fcos, fsin, kfull);

    // 6. q-absorb per head -> qfull[:, h, :512]  (fp16)
    gemm_f16_kernel<2><<<dim3(KVLORA / 128, ROWS / 128, Hh), blk, GSMEM>>>(
        q, Hh * QKH, QKH,
        wkvbT, NOPEc, (long)KVLORA * NOPEc,
        qfull, Hh * DF, DF,
        ROWS, KVLORA, NOPEc);

    // 7. qfull[:, h, 512:576] = rope(q_pe)  (fp16)
    ropeq_kernel<<<ROWS, 512>>>(q, fcos, fsin, qfull);

    // 8. flash attention -> ctx (fp16)
    attn_kernel<<<dim3(Ss / 32, Bb * Hh), 256, ATTN_SMEM_BYTES>>>(qfull, kfull, ctx);

    // 9. per-head out-proj: attnout = ctx_h @ wkvbV[h]^T -> fp16
    gemm_f16_kernel<2><<<dim3(1, ROWS / 128, Hh), blk, GSMEM>>>(
        ctx, Hh * KVLORA, KVLORA,
        wkvbV, KVLORA, (long)VDIMc * KVLORA,
        attnout, DIMc, VDIMc,
        ROWS, VDIMc, KVLORA);

    // 10. out = attnout @ wo_h^T       (4096 x 2048, K=2048) -> fp32
    gemm_f16_kernel<0><<<dim3(DIMc / 128, ROWS / 128, 1), blk, GSMEM>>>(
        attnout, DIMc, 0, wo_h, DIMc, 0, out, DIMc, 0, ROWS, DIMc, DIMc);
}

// round 17
// speedup vs baseline: 2.2828x; 1.0380x over previous
#include <cuda_runtime.h>
#include <cuda_fp16.h>
#include <math.h>
#include <stdint.h>

// ---------------- problem constants ----------------
#define Bb     2
#define Ss     2048
#define DIMc   2048
#define Hh     16
#define QLORA  1536
#define KVLORA 512
#define NOPEc  128
#define ROPEc  64
#define VDIMc  128
#define QKH    192            // NOPE + ROPE
#define ROWS   (Bb*Ss)        // 4096
#define DF     576            // 512 latent + 64 rope
#define SCALEc 0.07216878364870322f  // 1/sqrt(192)
#define EPSc   1e-6f

// ---------------- scratch (static device arrays; no allocation) ----------------
__device__ __half g_xh[(size_t)ROWS * DIMc];
__device__ __half g_wqa_h[(size_t)QLORA * DIMc];
__device__ __half g_wqb_h[(size_t)(Hh * QKH) * QLORA];
__device__ __half g_wkva_h[(size_t)DF * DIMc];
__device__ __half g_wo_h[(size_t)DIMc * DIMc];
__device__ float  g_qlat[(size_t)ROWS * QLORA];
__device__ __half g_qlat_h[(size_t)ROWS * QLORA];
__device__ __half g_q[(size_t)ROWS * (Hh * QKH)];
__device__ float  g_kv[(size_t)ROWS * DF];
__device__ __half g_kfull[(size_t)ROWS * DF];
__device__ __half g_qfull[(size_t)ROWS * Hh * DF];
__device__ __half g_ctx[(size_t)ROWS * Hh * KVLORA];
__device__ __half g_attnout[(size_t)ROWS * DIMc];
__device__ __half g_wkvbT[(size_t)Hh * KVLORA * NOPEc];
__device__ __half g_wkvbV[(size_t)Hh * VDIMc * KVLORA];

// ================= helpers =================
__device__ __forceinline__ void mma_f16(float* d, const uint32_t* a, const uint32_t* b) {
    asm volatile(
        "mma.sync.aligned.m16n8k16.row.col.f32.f16.f16.f32 "
        "{%0,%1,%2,%3}, {%4,%5,%6,%7}, {%8,%9}, {%0,%1,%2,%3};"
        : "+f"(d[0]), "+f"(d[1]), "+f"(d[2]), "+f"(d[3])
        : "r"(a[0]), "r"(a[1]), "r"(a[2]), "r"(a[3]), "r"(b[0]), "r"(b[1]));
}
__device__ __forceinline__ uint32_t smem_u32(const void* p) {
    uint32_t a;
    asm("{ .reg .u64 t; cvta.to.shared.u64 t, %1; cvt.u32.u64 %0, t; }" : "=r"(a) : "l"(p));
    return a;
}
__device__ __forceinline__ void cpa16(uint32_t dst, const void* src) {
    asm volatile("cp.async.cg.shared.global [%0], [%1], 16;" :: "r"(dst), "l"(src));
}
__device__ __forceinline__ void cpa16z(uint32_t dst, const void* src, uint32_t sz) {
    asm volatile("cp.async.cg.shared.global [%0], [%1], 16, %2;" :: "r"(dst), "l"(src), "r"(sz));
}
__device__ __forceinline__ void ldsm_x4(uint32_t* r, uint32_t addr) {
    asm volatile("ldmatrix.sync.aligned.m8n8.x4.shared.b16 {%0,%1,%2,%3}, [%4];"
                 : "=r"(r[0]), "=r"(r[1]), "=r"(r[2]), "=r"(r[3]) : "r"(addr));
}
__device__ __forceinline__ void ldsm_x2_trans(uint32_t& r0, uint32_t& r1, uint32_t addr) {
    asm volatile("ldmatrix.sync.aligned.m8n8.x2.trans.shared.b16 {%0,%1}, [%2];"
                 : "=r"(r0), "=r"(r1) : "r"(addr));
}

// ---------------- bulk fp32 -> fp16 convert ----------------
__global__ __launch_bounds__(256) void tohalf_kernel(
    const float4* __restrict__ src, uint4* __restrict__ dst, int n8)
{
    int i = blockIdx.x * 256 + threadIdx.x;
    if (i < n8) {
        float4 a = src[2 * i], b = src[2 * i + 1];
        __half2 h0 = __floats2half2_rn(a.x, a.y);
        __half2 h1 = __floats2half2_rn(a.z, a.w);
        __half2 h2 = __floats2half2_rn(b.x, b.y);
        __half2 h3 = __floats2half2_rn(b.z, b.w);
        uint4 o;
        o.x = *(uint32_t*)&h0; o.y = *(uint32_t*)&h1;
        o.z = *(uint32_t*)&h2; o.w = *(uint32_t*)&h3;
        dst[i] = o;
    }
}

// ---------------- wkv_b v-half -> fp16 contiguous copy [h][128][512] ----------------
__global__ __launch_bounds__(256) void wkvbv_kernel(
    const float* __restrict__ w, __half* __restrict__ out)
{
    int i = blockIdx.x * 256 + threadIdx.x;
    int n8 = Hh * VDIMc * KVLORA / 8;
    if (i < n8) {
        int per_h = VDIMc * KVLORA / 8;
        int h = i / per_h;
        int rem = i - h * per_h;
        const float4* src = (const float4*)(w + ((size_t)h * (NOPEc + VDIMc) + NOPEc) * KVLORA);
        float4 a = src[2 * rem], b = src[2 * rem + 1];
        __half2 h0 = __floats2half2_rn(a.x, a.y);
        __half2 h1 = __floats2half2_rn(a.z, a.w);
        __half2 h2 = __floats2half2_rn(b.x, b.y);
        __half2 h3 = __floats2half2_rn(b.z, b.w);
        uint4 o;
        o.x = *(uint32_t*)&h0; o.y = *(uint32_t*)&h1;
        o.z = *(uint32_t*)&h2; o.w = *(uint32_t*)&h3;
        ((uint4*)(out + (size_t)h * VDIMc * KVLORA))[rem] = o;
    }
}

// ================= fp16 tensor-core GEMM (TB: C = A @ B^T) =================
// 256 threads, 8 warps (2x4), 128x128 tile, BK=32 halfs, m16n8k16,
// 4-stage cp.async pipeline. Fragment loads via ldmatrix.x4 (conflict-free
// under the 4-word XOR swizzle). OUT: 0 = fp32, 2 = fp16.
#define GSMEM (16384 * 4)

template<int OUT>
__global__ __launch_bounds__(256) void gemm_f16_kernel(
    const __half* __restrict__ A, int lda, long sA_,
    const __half* __restrict__ B, int ldb, long sB_,
    void* __restrict__ Cv, int ldc, long sC_,
    int M, int N, int K)
{
    extern __shared__ __align__(16) uint32_t dsm[];

    int z = blockIdx.z;
    A += (size_t)z * sA_;
    B += (size_t)z * sB_;

    const int tid    = threadIdx.x;
    const int lane   = tid & 31;
    const int warp   = tid >> 5;
    const int warp_m = warp >> 2;
    const int warp_n = warp & 3;
    const int g = lane >> 2, t = lane & 3;
    const int m0 = blockIdx.y * 128;
    const int n0 = blockIdx.x * 128;
    const int KT = K >> 5;

    float acc[4][4][4];
#pragma unroll
    for (int mt = 0; mt < 4; mt++)
#pragma unroll
        for (int nt = 0; nt < 4; nt++)
#pragma unroll
            for (int e = 0; e < 4; e++) acc[mt][nt][e] = 0.f;

    const int lr0 = tid >> 2;
    const int lkw = (tid & 3) << 2;
    const uint32_t smem_base = smem_u32(dsm);

    // ---- precomputed ldmatrix byte offsets (within one stage) ----
    uint32_t a_off[4][2], b_off[2][2];
    {
        int ar = warp_m * 64 + (lane & 15);
        int ach = lane >> 4;                 // k-chunk select
#pragma unroll
        for (int mt = 0; mt < 4; mt++) {
            int r = ar + mt * 16;
            int swz = ((r >> 1) & 3) << 2;
#pragma unroll
            for (int ks = 0; ks < 2; ks++)
                a_off[mt][ks] = (uint32_t)(r * 64 + (((ks * 8 + ach * 4) ^ swz) << 2));
        }
        int br = warp_n * 32 + ((lane >> 4) & 1) * 8 + (lane & 7);
        int bch = (lane >> 3) & 1;
#pragma unroll
        for (int ntp = 0; ntp < 2; ntp++) {
            int r = br + ntp * 16;
            int swz = ((r >> 1) & 3) << 2;
#pragma unroll
            for (int ks = 0; ks < 2; ks++)
                b_off[ntp][ks] = (uint32_t)(r * 64 + (((ks * 8 + bch * 4) ^ swz) << 2));
        }
    }

    auto load_stage = [&](int chunk, int s) {
        int k0 = chunk << 5;
        uint32_t abase = smem_base + (uint32_t)s * 8192;
        uint32_t bbase = abase + 32768;
#pragma unroll
        for (int i = 0; i < 2; i++) {
            int r = lr0 + i * 64;
            uint32_t off = (uint32_t)(r * 16 + (lkw ^ (((r >> 1) & 3) << 2))) * 4;
            cpa16(abase + off, A + (size_t)(m0 + r) * lda + k0 + lkw * 2);
            cpa16z(bbase + off, B + (size_t)(n0 + r) * ldb + k0 + lkw * 2,
                   (n0 + r < N) ? 16u : 0u);
        }
    };

    auto compute = [&](int s) {
        uint32_t abase = smem_base + (uint32_t)s * 8192;
        uint32_t bbase = abase + 32768;
#pragma unroll
        for (int ks = 0; ks < 2; ks++) {
            uint32_t af[4][4];
            uint32_t bf[4][2];
#pragma unroll
            for (int mt = 0; mt < 4; mt++)
                ldsm_x4(af[mt], abase + a_off[mt][ks]);
#pragma unroll
            for (int ntp = 0; ntp < 2; ntp++) {
                uint32_t r4[4];
                ldsm_x4(r4, bbase + b_off[ntp][ks]);
                bf[2 * ntp][0] = r4[0]; bf[2 * ntp][1] = r4[1];
                bf[2 * ntp + 1][0] = r4[2]; bf[2 * ntp + 1][1] = r4[3];
            }
#pragma unroll
            for (int mt = 0; mt < 4; mt++)
#pragma unroll
                for (int nt = 0; nt < 4; nt++)
                    mma_f16(acc[mt][nt], af[mt], bf[nt]);
        }
    };

    const int PRE = (KT < 3) ? KT : 3;
    for (int s = 0; s < PRE; s++) {
        load_stage(s, s);
        asm volatile("cp.async.commit_group;" ::: "memory");
    }

    for (int kt = 0; kt < KT; kt++) {
        asm volatile("cp.async.wait_group 2;" ::: "memory");
        __syncthreads();
        if (kt + 3 < KT) load_stage(kt + 3, (kt + 3) & 3);
        asm volatile("cp.async.commit_group;" ::: "memory");
        compute(kt & 3);
    }

#pragma unroll
    for (int mt = 0; mt < 4; mt++) {
        int row0 = m0 + warp_m * 64 + mt * 16 + g;
#pragma unroll
        for (int nt = 0; nt < 4; nt++) {
            int col = n0 + warp_n * 32 + nt * 8 + 2 * t;
            if (col < N) {
                if (OUT == 2) {
                    __half* C = (__half*)Cv + (size_t)z * sC_;
                    *(__half2*)(C + (size_t)row0 * ldc + col) =
                        __floats2half2_rn(acc[mt][nt][0], acc[mt][nt][1]);
                    *(__half2*)(C + (size_t)(row0 + 8) * ldc + col) =
                        __floats2half2_rn(acc[mt][nt][2], acc[mt][nt][3]);
                } else {
                    float* C = (float*)Cv + (size_t)z * sC_;
                    *(float2*)(C + (size_t)row0 * ldc + col) =
                        make_float2(acc[mt][nt][0], acc[mt][nt][1]);
                    *(float2*)(C + (size_t)(row0 + 8) * ldc + col) =
                        make_float2(acc[mt][nt][2], acc[mt][nt][3]);
                }
            }
        }
    }
}

// ---------------- transpose wkv_b nope half -> fp16 ----------------
__global__ __launch_bounds__(256) void transpose_wkvb_kernel(
    const float* __restrict__ w, __half* __restrict__ out)
{
    __shared__ float tile[32][33];
    int h = blockIdx.z;
    int c0 = blockIdx.x * 32;
    int d0 = blockIdx.y * 32;
    int tx = threadIdx.x & 31, ty = threadIdx.x >> 5;
#pragma unroll
    for (int i = ty; i < 32; i += 8)
        tile[i][tx] = w[((size_t)h * 256 + d0 + i) * KVLORA + c0 + tx];
    __syncthreads();
#pragma unroll
    for (int i = ty; i < 32; i += 8)
        out[((size_t)h * KVLORA + c0 + i) * NOPEc + d0 + tx] = __float2half_rn(tile[tx][i]);
}

// ---------------- RMSNorm: fp32 in -> fp16 out ----------------
__global__ __launch_bounds__(256) void rmsnorm_h_kernel(
    const float* __restrict__ x, const float* __restrict__ w,
    __half* __restrict__ out, int L)
{
    __shared__ float sbuf[8];
    int row = blockIdx.x;
    const float* xr = x + (size_t)row * L;
    __half* orow = out + (size_t)row * L;
    float ss = 0.f;
    for (int i = threadIdx.x; i < L; i += 256) { float v = xr[i]; ss += v * v; }
#pragma unroll
    for (int o = 16; o; o >>= 1) ss += __shfl_xor_sync(0xffffffffu, ss, o);
    int warp = threadIdx.x >> 5, lane = threadIdx.x & 31;
    if (lane == 0) sbuf[warp] = ss;
    __syncthreads();
    if (threadIdx.x == 0) {
        float t = 0.f;
#pragma unroll
        for (int i = 0; i < 8; i++) t += sbuf[i];
        sbuf[0] = rsqrtf(t / (float)L + EPSc);
    }
    __syncthreads();
    float sc = sbuf[0];
    for (int i = threadIdx.x; i < L; i += 256) orow[i] = __float2half_rn(xr[i] * sc * w[i]);
}

// ---------------- kv split: rmsnorm(latent) + rope(k_pe) -> kfull (fp16) ----------------
__global__ __launch_bounds__(256) void kvprep_kernel(
    const float* __restrict__ kv, const float* __restrict__ w,
    const float* __restrict__ fcos, const float* __restrict__ fsin,
    __half* __restrict__ kfull)
{
    __shared__ float sbuf[8];
    int row = blockIdx.x;
    int s = row & (Ss - 1);
    const float* kr = kv + (size_t)row * DF;
    __half* kf = kfull + (size_t)row * DF;

    float ss = 0.f;
    for (int i = threadIdx.x; i < KVLORA; i += 256) { float v = kr[i]; ss += v * v; }
#pragma unroll
    for (int o = 16; o; o >>= 1) ss += __shfl_xor_sync(0xffffffffu, ss, o);
    int warp = threadIdx.x >> 5, lane = threadIdx.x & 31;
    if (lane == 0) sbuf[warp] = ss;
    __syncthreads();
    if (threadIdx.x == 0) {
        float t = 0.f;
#pragma unroll
        for (int i = 0; i < 8; i++) t += sbuf[i];
        sbuf[0] = rsqrtf(t / (float)KVLORA + EPSc);
    }
    __syncthreads();
    float sc = sbuf[0];
    for (int i = threadIdx.x; i < KVLORA; i += 256) kf[i] = __float2half_rn(kr[i] * sc * w[i]);

    if (threadIdx.x < 32) {
        int i = threadIdx.x;
        float x0 = kr[KVLORA + 2 * i], x1 = kr[KVLORA + 2 * i + 1];
        float c = fcos[s * 32 + i], sn = fsin[s * 32 + i];
        kf[KVLORA + 2 * i]     = __float2half_rn(x0 * c - x1 * sn);
        kf[KVLORA + 2 * i + 1] = __float2half_rn(x0 * sn + x1 * c);
    }
}

// ---------------- rope(q_pe): fp16 q in -> qfull[:, :, 512:576] (fp16) ----------------
__global__ __launch_bounds__(512) void ropeq_kernel(
    const __half* __restrict__ q, const float* __restrict__ fcos,
    const float* __restrict__ fsin, __half* __restrict__ qfull)
{
    int row = blockIdx.x;
    int s = row & (Ss - 1);
    int t = threadIdx.x;
    int h = t >> 5, i = t & 31;
    const __half* qr = q + (size_t)row * (Hh * QKH) + h * QKH + NOPEc;
    float x0 = __half2float(qr[2 * i]), x1 = __half2float(qr[2 * i + 1]);
    float c = fcos[s * 32 + i], sn = fsin[s * 32 + i];
    __half* dst = qfull + ((size_t)row * Hh + h) * DF + KVLORA;
    dst[2 * i]     = __float2half_rn(x0 * c - x1 * sn);
    dst[2 * i + 1] = __float2half_rn(x0 * sn + x1 * c);
}

// ---------------- flash attention (fp16 mma, ldmatrix fragments) ----------------
#define HSTR 584
#define PSTRF 36
#define PHSTR 72
#define QS_OFF   0
#define KS_OFF   (32 * HSTR * 2)
#define PS_OFF   (2 * 32 * HSTR * 2)
#define PH_OFF   (PS_OFF + 4 * 32 * PSTRF * 4)
#define AROW_OFF (PH_OFF + 32 * PHSTR * 2)
#define ATTN_SMEM_BYTES (AROW_OFF + 64 * 4)

__global__ __launch_bounds__(256, 2) void attn_kernel(
    const __half* __restrict__ qfull, const __half* __restrict__ kfull,
    __half* __restrict__ ctx)
{
    extern __shared__ char smraw[];
    __half* Qs   = (__half*)(smraw + QS_OFF);
    __half* Ks   = (__half*)(smraw + KS_OFF);
    float*  Ps   = (float*)(smraw + PS_OFF);
    __half* Ph   = (__half*)(smraw + PH_OFF);
    float*  arow = (float*)(smraw + AROW_OFF);
    float*  lrow = arow + 32;

    const int tid  = threadIdx.x;
    const int lane = tid & 31, warp = tid >> 5;
    const int g = lane >> 2, t = lane & 3;
    const int wk = warp & 3, wm = warp >> 2;
    const int bh = blockIdx.y;
    const int b = bh >> 4, h = bh & 15;
    const int s0 = blockIdx.x * 32;

    const int trow = tid >> 3, t8 = tid & 7;
    const uint32_t qdst = smem_u32(Qs) + (uint32_t)trow * (HSTR * 2) + (uint32_t)t8 * 16;
    const uint32_t kdst = smem_u32(Ks) + (uint32_t)trow * (HSTR * 2) + (uint32_t)t8 * 16;

    // ldmatrix address precompute
    const uint32_t qa_base = smem_u32(Qs) + (uint32_t)(wm * 16 + (lane & 15)) * (HSTR * 2)
                             + (uint32_t)wk * 288 + (uint32_t)(lane >> 4) * 16;
    const uint32_t kb_base = smem_u32(Ks)
                             + (uint32_t)(((lane >> 4) & 1) * 8 + (lane & 7)) * (HSTR * 2)
                             + (uint32_t)wk * 288 + (uint32_t)((lane >> 3) & 1) * 16;
    const uint32_t pa_base = smem_u32(Ph) + (uint32_t)(lane & 15) * (PHSTR * 2)
                             + (uint32_t)(lane >> 4) * 16;

    // ---- load Q tile ----
    {
        const char* src = (const char*)(qfull + ((size_t)(b * Ss + s0 + trow) * Hh + h) * DF) + t8 * 16;
#pragma unroll
        for (int c = 0; c < 9; c++) cpa16(qdst + c * 128, src + c * 128);
        asm volatile("cp.async.commit_group;" ::: "memory");
    }

    float oacc[2][8][4];
#pragma unroll
    for (int mt = 0; mt < 2; mt++)
#pragma unroll
        for (int nt = 0; nt < 8; nt++)
#pragma unroll
            for (int e = 0; e < 4; e++) oacc[mt][nt][e] = 0.f;

    float mreg[4], lreg[4];
#pragma unroll
    for (int ii = 0; ii < 4; ii++) { mreg[ii] = -INFINITY; lreg[ii] = 0.f; }

    const int ntiles = s0 / 32 + 1;
    for (int kt = 0; kt < ntiles; kt++) {
        int t0 = kt * 32;
        // ---- load K tile ----
        {
            const char* src = (const char*)(kfull + (size_t)(b * Ss + t0 + trow) * DF) + t8 * 16;
#pragma unroll
            for (int c = 0; c < 9; c++) cpa16(kdst + c * 128, src + c * 128);
            asm volatile("cp.async.commit_group;" ::: "memory");
            asm volatile("cp.async.wait_group 0;" ::: "memory");
        }
        __syncthreads();

        // ---- scores: warp (wm, wk) -> m16 x n32, k-quarter 144 halfs (9 K16 steps) ----
        {
            float sacc[4][4];
#pragma unroll
            for (int nt = 0; nt < 4; nt++)
#pragma unroll
                for (int e = 0; e < 4; e++) sacc[nt][e] = 0.f;

#pragma unroll 3
            for (int ks = 0; ks < 9; ks++) {
                uint32_t a[4];
                ldsm_x4(a, qa_base + ks * 32);
                uint32_t bf[4][2];
#pragma unroll
                for (int ntp = 0; ntp < 2; ntp++) {
                    uint32_t r4[4];
                    ldsm_x4(r4, kb_base + (uint32_t)ntp * (16 * HSTR * 2) + ks * 32);
                    bf[2 * ntp][0] = r4[0]; bf[2 * ntp][1] = r4[1];
                    bf[2 * ntp + 1][0] = r4[2]; bf[2 * ntp + 1][1] = r4[3];
                }
#pragma unroll
                for (int nt = 0; nt < 4; nt++)
                    mma_f16(sacc[nt], a, bf[nt]);
            }
            float* Pw = Ps + wk * 32 * PSTRF;
#pragma unroll
            for (int nt = 0; nt < 4; nt++) {
                int colb = nt * 8 + 2 * t;
                *(float2*)&Pw[(wm * 16 + g) * PSTRF + colb] =
                    make_float2(sacc[nt][0], sacc[nt][1]);
                *(float2*)&Pw[(wm * 16 + g + 8) * PSTRF + colb] =
                    make_float2(sacc[nt][2], sacc[nt][3]);
            }
        }
        __syncthreads();

        // ---- softmax: warp owns rows 4*warp..+3, lane = key j ----
        {
#pragma unroll
            for (int ii = 0; ii < 4; ii++) {
                int i = warp * 4 + ii;
                float v = (Ps[i * PSTRF + lane] +
                           Ps[32 * PSTRF + i * PSTRF + lane] +
                           Ps[64 * PSTRF + i * PSTRF + lane] +
                           Ps[96 * PSTRF + i * PSTRF + lane]) * SCALEc;
                if (t0 + lane > s0 + i) v = -INFINITY;
                float mx = v;
#pragma unroll
                for (int o = 16; o; o >>= 1) mx = fmaxf(mx, __shfl_xor_sync(0xffffffffu, mx, o));
                float mnew = fmaxf(mreg[ii], mx);
                float p = __expf(v - mnew);
                float psum = p;
#pragma unroll
                for (int o = 16; o; o >>= 1) psum += __shfl_xor_sync(0xffffffffu, psum, o);
                float al = __expf(mreg[ii] - mnew);
                lreg[ii] = lreg[ii] * al + psum;
                mreg[ii] = mnew;
                Ph[i * PHSTR + lane] = __float2half_rn(p);
                if (lane == 0) arow[i] = al;
            }
        }
        __syncthreads();

        // ---- PV: warp owns all 32 rows x cols [warp*64, warp*64+64) ----
        {
#pragma unroll
            for (int mt = 0; mt < 2; mt++) {
                float al0 = arow[mt * 16 + g];
                float al1 = arow[mt * 16 + g + 8];
#pragma unroll
                for (int nt = 0; nt < 8; nt++) {
                    oacc[mt][nt][0] *= al0; oacc[mt][nt][1] *= al0;
                    oacc[mt][nt][2] *= al1; oacc[mt][nt][3] *= al1;
                }
            }
#pragma unroll
            for (int jb = 0; jb < 2; jb++) {
                int j0 = jb * 16;
                uint32_t pa[2][4];
#pragma unroll
                for (int mt = 0; mt < 2; mt++)
                    ldsm_x4(pa[mt], pa_base + (uint32_t)mt * (16 * PHSTR * 2) + j0 * 2);
                uint32_t vbase = smem_u32(Ks) +
                    (uint32_t)(j0 + (lane & 15)) * (HSTR * 2) + (uint32_t)(warp * 64) * 2;
#pragma unroll
                for (int nt = 0; nt < 8; nt++) {
                    uint32_t vb[2];
                    ldsm_x2_trans(vb[0], vb[1], vbase + nt * 16);
                    mma_f16(oacc[0][nt], pa[0], vb);
                    mma_f16(oacc[1][nt], pa[1], vb);
                }
            }
        }
        __syncthreads();
    }

    // ---- publish l, normalize, store ctx (fp16) ----
    if (lane == 0) {
#pragma unroll
        for (int ii = 0; ii < 4; ii++) lrow[warp * 4 + ii] = lreg[ii];
    }
    __syncthreads();
#pragma unroll
    for (int mt = 0; mt < 2; mt++) {
        int r0 = mt * 16 + g;
        int r1 = mt * 16 + g + 8;
        float inv0 = 1.0f / lrow[r0];
        float inv1 = 1.0f / lrow[r1];
        __half* cp0 = ctx + ((size_t)(b * Ss + s0 + r0) * Hh + h) * KVLORA + warp * 64;
        __half* cp1 = ctx + ((size_t)(b * Ss + s0 + r1) * Hh + h) * KVLORA + warp * 64;
#pragma unroll
        for (int nt = 0; nt < 8; nt++) {
            int col = nt * 8 + 2 * t;
            *(__half2*)(cp0 + col) =
                __floats2half2_rn(oacc[mt][nt][0] * inv0, oacc[mt][nt][1] * inv0);
            *(__half2*)(cp1 + col) =
                __floats2half2_rn(oacc[mt][nt][2] * inv1, oacc[mt][nt][3] * inv1);
        }
    }
}

// ---------------- launch ----------------
extern "C" void kernel_launch(void* const* d_in, const int* in_sizes, int n_in,
                              void* d_out, int out_size)
{
    const float* x     = (const float*)d_in[0];
    const float* fcos  = (const float*)d_in[1];
    const float* fsin  = (const float*)d_in[2];
    // d_in[3] = mask (causal; handled analytically)
    const float* wq_a  = (const float*)d_in[4];
    const float* q_ln  = (const float*)d_in[5];
    const float* wq_b  = (const float*)d_in[6];
    const float* wkv_a = (const float*)d_in[7];
    const float* kv_ln = (const float*)d_in[8];
    const float* wkv_b = (const float*)d_in[9];
    const float* wo    = (const float*)d_in[10];
    float* out = (float*)d_out;

    __half *xh, *wqa_h, *wqb_h, *wkva_h, *wo_h, *qlat_h, *q, *ctx, *attnout, *wkvbT, *wkvbV;
    __half *kfull, *qfull;
    float *qlat, *kv;
    cudaGetSymbolAddress((void**)&xh,      g_xh);
    cudaGetSymbolAddress((void**)&wqa_h,   g_wqa_h);
    cudaGetSymbolAddress((void**)&wqb_h,   g_wqb_h);
    cudaGetSymbolAddress((void**)&wkva_h,  g_wkva_h);
    cudaGetSymbolAddress((void**)&wo_h,    g_wo_h);
    cudaGetSymbolAddress((void**)&qlat,    g_qlat);
    cudaGetSymbolAddress((void**)&qlat_h,  g_qlat_h);
    cudaGetSymbolAddress((void**)&q,       g_q);
    cudaGetSymbolAddress((void**)&kv,      g_kv);
    cudaGetSymbolAddress((void**)&kfull,   g_kfull);
    cudaGetSymbolAddress((void**)&qfull,   g_qfull);
    cudaGetSymbolAddress((void**)&ctx,     g_ctx);
    cudaGetSymbolAddress((void**)&attnout, g_attnout);
    cudaGetSymbolAddress((void**)&wkvbT,   g_wkvbT);
    cudaGetSymbolAddress((void**)&wkvbV,   g_wkvbV);

    cudaFuncSetAttribute(gemm_f16_kernel<0>, cudaFuncAttributeMaxDynamicSharedMemorySize, GSMEM);
    cudaFuncSetAttribute(gemm_f16_kernel<2>, cudaFuncAttributeMaxDynamicSharedMemorySize, GSMEM);
    cudaFuncSetAttribute(attn_kernel, cudaFuncAttributeMaxDynamicSharedMemorySize,
                         ATTN_SMEM_BYTES);

    dim3 blk(256);

    auto tohalf = [&](const float* s, __half* d, size_t n) {
        int n8 = (int)(n / 8);
        tohalf_kernel<<<(n8 + 255) / 256, blk>>>((const float4*)s, (uint4*)d, n8);
    };
    tohalf(x,     xh,     (size_t)ROWS * DIMc);
    tohalf(wq_a,  wqa_h,  (size_t)QLORA * DIMc);
    tohalf(wq_b,  wqb_h,  (size_t)(Hh * QKH) * QLORA);
    tohalf(wkv_a, wkva_h, (size_t)DF * DIMc);
    tohalf(wo,    wo_h,   (size_t)DIMc * DIMc);
    wkvbv_kernel<<<(Hh * VDIMc * KVLORA / 8 + 255) / 256, blk>>>(wkv_b, wkvbV);
    transpose_wkvb_kernel<<<dim3(KVLORA / 32, NOPEc / 32, Hh), blk>>>(wkv_b, wkvbT);

    // 1. q_lat_pre = xh @ wqa_h^T      -> fp32
    gemm_f16_kernel<0><<<dim3(QLORA / 128, ROWS / 128, 1), blk, GSMEM>>>(
        xh, DIMc, 0, wqa_h, DIMc, 0, qlat, QLORA, 0, ROWS, QLORA, DIMc);

    // 2. rmsnorm -> fp16
    rmsnorm_h_kernel<<<ROWS, 256>>>(qlat, q_ln, qlat_h, QLORA);

    // 3. q = qlat_h @ wqb_h^T          -> fp16
    gemm_f16_kernel<2><<<dim3((Hh * QKH) / 128, ROWS / 128, 1), blk, GSMEM>>>(
        qlat_h, QLORA, 0, wqb_h, QLORA, 0, q, Hh * QKH, 0, ROWS, Hh * QKH, QLORA);

    // 4. kv = xh @ wkva_h^T            -> fp32
    gemm_f16_kernel<0><<<dim3((DF + 127) / 128, ROWS / 128, 1), blk, GSMEM>>>(
        xh, DIMc, 0, wkva_h, DIMc, 0, kv, DF, 0, ROWS, DF, DIMc);

    // 5. kfull = [rmsnorm(kv_lat), rope(k_pe)]  (fp16)
    kvprep_kernel<<<ROWS, 256>>>(kv, kv_ln, fcos, fsin, kfull);

    // 6. q-absorb per head -> qfull[:, h, :512]  (fp16)
    gemm_f16_kernel<2><<<dim3(KVLORA / 128, ROWS / 128, Hh), blk, GSMEM>>>(
        q, Hh * QKH, QKH,
        wkvbT, NOPEc, (long)KVLORA * NOPEc,
        qfull, Hh * DF, DF,
        ROWS, KVLORA, NOPEc);

    // 7. qfull[:, h, 512:576] = rope(q_pe)  (fp16)
    ropeq_kernel<<<ROWS, 512>>>(q, fcos, fsin, qfull);

    // 8. flash attention -> ctx (fp16)
    attn_kernel<<<dim3(Ss / 32, Bb * Hh), 256, ATTN_SMEM_BYTES>>>(qfull, kfull, ctx);

    // 9. per-head out-proj: attnout = ctx_h @ wkvbV[h]^T -> fp16
    gemm_f16_kernel<2><<<dim3(1, ROWS / 128, Hh), blk, GSMEM>>>(
        ctx, Hh * KVLORA, KVLORA,
        wkvbV, KVLORA, (long)VDIMc * KVLORA,
        attnout, DIMc, VDIMc,
        ROWS, VDIMc, KVLORA);

    // 10. out = attnout @ wo_h^T       -> fp32
    gemm_f16_kernel<0><<<dim3(DIMc / 128, ROWS / 128, 1), blk, GSMEM>>>(
        attnout, DIMc, 0, wo_h, DIMc, 0, out, DIMc, 0, ROWS, DIMc, DIMc);
}